// round 14
// baseline (speedup 1.0000x reference)
#include <cuda_runtime.h>
#include <math.h>
#include <stdint.h>

#define N0C 50000
#define E0C 800000
#define N1C 10000
#define E1C 160000
#define FC  128
#define HC  256
#define BC  64

// ---------------- static scratch ----------------
__device__ float g_xw [N0C * HC];
__device__ float g_x1 [N0C * HC];
__device__ float g_x2 [N0C * HC];
__device__ float g_h  [N0C * HC];
__device__ float g_dinv0[N0C];
__device__ float g_coef0[E0C];

__device__ float g_h1cat[N1C * 2 * HC];
__device__ float g_yw [N1C * HC];
__device__ float g_y1 [N1C * HC];
__device__ float g_y2 [N1C * HC];
__device__ float g_hb [N1C * HC];
__device__ float g_dinv1[N1C];
__device__ float g_coef1[E1C];

__device__ float g_z [BC * 4 * HC];

// CSR scratch
__device__ int   g_cnt0[N0C];
__device__ int   g_start0[N0C + 1];
__device__ int   g_cur0[N0C];
__device__ int   g_srow0[E0C];
__device__ float g_scoef0[E0C];
__device__ int   g_cnt1[N1C];
__device__ int   g_start1[N1C + 1];
__device__ int   g_cur1[N1C];
__device__ int   g_srow1[E1C];
__device__ float g_scoef1[E1C];

// ---------------- utility kernels ----------------
__global__ void fill_kernel(float* p, int n, float v) {
    int i = blockIdx.x * blockDim.x + threadIdx.x;
    if (i < n) p[i] = v;
}

__global__ void filli_kernel(int* p, int n, int v) {
    int i = blockIdx.x * blockDim.x + threadIdx.x;
    if (i < n) p[i] = v;
}

__global__ void deg_accum_kernel(const int* __restrict__ col,
                                 const float* __restrict__ ew,
                                 float* __restrict__ deg, int E) {
    int e = blockIdx.x * blockDim.x + threadIdx.x;
    if (e < E) atomicAdd(&deg[col[e]], ew[e]);
}

__global__ void finalize_dinv_kernel(float* deg, int n) {
    int i = blockIdx.x * blockDim.x + threadIdx.x;
    if (i < n) {
        float d = deg[i];
        deg[i] = (d > 0.f) ? rsqrtf(d) : 0.f;
    }
}

__global__ void edge_coef_kernel(const int* __restrict__ row,
                                 const int* __restrict__ col,
                                 const float* __restrict__ ew,
                                 const float* __restrict__ dinv,
                                 float* __restrict__ coef, int E) {
    int e = blockIdx.x * blockDim.x + threadIdx.x;
    if (e < E) coef[e] = dinv[row[e]] * ew[e] * dinv[col[e]];
}

// ---------------- CSR build ----------------
__global__ void count_kernel(const int* __restrict__ col,
                             int* __restrict__ cnt, int E) {
    int e = blockIdx.x * blockDim.x + threadIdx.x;
    if (e < E) atomicAdd(&cnt[col[e]], 1);
}

__global__ void scan_kernel(const int* __restrict__ cnt,
                            int* __restrict__ start,
                            int* __restrict__ cursor, int n) {
    __shared__ int part[1024];
    int tid = threadIdx.x;
    int chunk = (n + 1023) / 1024;
    int base = tid * chunk;
    int s = 0;
    for (int i = 0; i < chunk; i++) {
        int idx = base + i;
        if (idx < n) s += cnt[idx];
    }
    part[tid] = s;
    __syncthreads();
    for (int off = 1; off < 1024; off <<= 1) {
        int v = (tid >= off) ? part[tid - off] : 0;
        __syncthreads();
        part[tid] += v;
        __syncthreads();
    }
    int run = (tid == 0) ? 0 : part[tid - 1];
    for (int i = 0; i < chunk; i++) {
        int idx = base + i;
        if (idx < n) {
            start[idx] = run;
            cursor[idx] = run;
            run += cnt[idx];
        }
    }
    if (tid == 1023) start[n] = run;
}

__global__ void emit_kernel(const int* __restrict__ row,
                            const int* __restrict__ col,
                            const float* __restrict__ coef,
                            int* __restrict__ cursor,
                            int* __restrict__ srow,
                            float* __restrict__ scoef, int E) {
    int e = blockIdx.x * blockDim.x + threadIdx.x;
    if (e < E) {
        int c = col[e];
        int p = atomicAdd(&cursor[c], 1);
        srow[p] = row[e];
        scoef[p] = coef[e];
    }
}

// Gather-by-destination: out[c,:] += sum_e coef*xw[row,:]. No output atomics.
__global__ void gcn_gather_csr(const float* __restrict__ xw,
                               const int* __restrict__ srow,
                               const float* __restrict__ scoef,
                               const int* __restrict__ start,
                               float* __restrict__ out, int N) {
    int f4 = threadIdx.x & 63;
    int slot = threadIdx.x >> 6;
    int c = blockIdx.x * 4 + slot;
    if (c >= N) return;
    int p  = start[c];
    int pe = start[c + 1];
    float4 acc = make_float4(0.f, 0.f, 0.f, 0.f);
    for (; p + 1 < pe; p += 2) {
        int r0 = srow[p],     r1 = srow[p + 1];
        float c0 = scoef[p],  c1 = scoef[p + 1];
        float4 v0 = *reinterpret_cast<const float4*>(xw + (size_t)r0 * HC + f4 * 4);
        float4 v1 = *reinterpret_cast<const float4*>(xw + (size_t)r1 * HC + f4 * 4);
        acc.x += c0 * v0.x + c1 * v1.x;
        acc.y += c0 * v0.y + c1 * v1.y;
        acc.z += c0 * v0.z + c1 * v1.z;
        acc.w += c0 * v0.w + c1 * v1.w;
    }
    if (p < pe) {
        int r = srow[p];
        float cf = scoef[p];
        float4 v = *reinterpret_cast<const float4*>(xw + (size_t)r * HC + f4 * 4);
        acc.x += cf * v.x; acc.y += cf * v.y;
        acc.z += cf * v.z; acc.w += cf * v.w;
    }
    float4* dst = reinterpret_cast<float4*>(out + (size_t)c * HC + f4 * 4);
    float4 cur = *dst;
    cur.x += acc.x; cur.y += acc.y; cur.z += acc.z; cur.w += acc.w;
    *dst = cur;
}

// ---------------- bf16 3-term tensor-core GEMM, 128x64 tile, 3 CTAs/SM ----
#define GBM 128
#define GBN 64
// word offsets within one buffer
#define S_AHI 0
#define S_ALO 1024
#define S_BHI 2048
#define S_BLO 2560
#define S_BUF 3072

__device__ __forceinline__ void split_pair(float fx, float fy,
                                           uint32_t& hi, uint32_t& lo) {
    asm("cvt.rn.bf16x2.f32 %0, %1, %2;" : "=r"(hi) : "f"(fy), "f"(fx));
    float hx = __uint_as_float(hi << 16);
    float hy = __uint_as_float(hi & 0xFFFF0000u);
    float rx = fx - hx;
    float ry = fy - hy;
    asm("cvt.rn.bf16x2.f32 %0, %1, %2;" : "=r"(lo) : "f"(ry), "f"(rx));
}

__device__ __forceinline__ void mma_bf16(float* c, const uint32_t* a, const uint32_t* b) {
    asm volatile(
        "mma.sync.aligned.m16n8k16.row.col.f32.bf16.bf16.f32 "
        "{%0,%1,%2,%3}, {%4,%5,%6,%7}, {%8,%9}, {%0,%1,%2,%3};"
        : "+f"(c[0]), "+f"(c[1]), "+f"(c[2]), "+f"(c[3])
        : "r"(a[0]), "r"(a[1]), "r"(a[2]), "r"(a[3]), "r"(b[0]), "r"(b[1]));
}

__device__ __forceinline__ int a_swz(int lin) {
    return lin ^ (((lin >> 5) & 3) << 2);
}

__global__ __launch_bounds__(256, 3)
void gemm_tc_kernel(const float* __restrict__ A1,
                    const float* __restrict__ A2,
                    int K1, int K,
                    const float* __restrict__ W,
                    const float* __restrict__ bias,
                    float* __restrict__ C,
                    float* __restrict__ C2,
                    const float* __restrict__ dinv,
                    int M, int N,
                    int reluIn, int reluOut) {
    extern __shared__ uint32_t smem[];

    const int tid  = threadIdx.x;
    const int lane = tid & 31;
    const int warp = tid >> 5;
    const int warp_m = warp & 3;     // 4 warps in M (32 rows each)
    const int warp_n = warp >> 2;    // 2 warps in N (32 cols each)
    const int bm = blockIdx.y * GBM;
    const int bn = blockIdx.x * GBN;
    const int K2 = K - K1;

    // A staging (all 256 threads): row = tid>>1, kpairs (tid&1)*4 .. +3
    const int am     = tid >> 1;
    const int ak0    = (tid & 1) * 8;
    const int amtile = am >> 4;
    const int ar     = am & 15;
    const int abase  = amtile * 128 + (ar & 7) * 16 + (ar >> 3);

    // B staging (threads 0..127): kpair = tid>>4 (0..7), cols (tid&15)*4
    const int bkp  = tid >> 4;
    const int bn0  = (tid & 15) * 4;
    const int bkt  = (bkp & 3) * 2 + (bkp >> 2);
    const bool bAct = (tid < 128);

    float c[2][4][4];
#pragma unroll
    for (int mi = 0; mi < 2; mi++)
#pragma unroll
        for (int ni = 0; ni < 4; ni++)
#pragma unroll
            for (int q = 0; q < 4; q++) c[mi][ni][q] = 0.f;

    const int nt = K / 16;

    float4 va[2], vw[2];
    auto LOAD_TILE = [&](int t) {
        const int gk0 = t * 16;
#pragma unroll
        for (int i = 0; i < 2; i++) {
            int gk = gk0 + ak0 + i * 4;
            int gm = bm + am;
            float4 v = make_float4(0.f, 0.f, 0.f, 0.f);
            if (gm < M) {
                const float* src = (gk < K1) ? (A1 + (size_t)gm * K1 + gk)
                                             : (A2 + (size_t)gm * K2 + (gk - K1));
                v = *reinterpret_cast<const float4*>(src);
            }
            if (reluIn) {
                v.x = fmaxf(v.x, 0.f); v.y = fmaxf(v.y, 0.f);
                v.z = fmaxf(v.z, 0.f); v.w = fmaxf(v.w, 0.f);
            }
            va[i] = v;
        }
        if (bAct) {
            int r0 = gk0 + 2 * bkp;
            vw[0] = *reinterpret_cast<const float4*>(W + (size_t)r0 * N + bn + bn0);
            vw[1] = *reinterpret_cast<const float4*>(W + (size_t)(r0 + 1) * N + bn + bn0);
        }
    };

    auto STORE_TILE = [&](int buf) {
        uint32_t* sb = smem + buf * S_BUF;
#pragma unroll
        for (int i = 0; i < 2; i++) {
            int p = (ak0 >> 1) + 2 * i;
            uint32_t h, l;
            split_pair(va[i].x, va[i].y, h, l);
            int lin = abase + (p & 3) * 4 + (p >> 2) * 2;
            int sw = a_swz(lin);
            sb[S_AHI + sw] = h;
            sb[S_ALO + sw] = l;
            split_pair(va[i].z, va[i].w, h, l);
            p++;
            lin = abase + (p & 3) * 4 + (p >> 2) * 2;
            sw = a_swz(lin);
            sb[S_AHI + sw] = h;
            sb[S_ALO + sw] = l;
        }
        if (bAct) {
            float f0[4] = {vw[0].x, vw[0].y, vw[0].z, vw[0].w};
            float f1[4] = {vw[1].x, vw[1].y, vw[1].z, vw[1].w};
#pragma unroll
            for (int q = 0; q < 4; q++) {
                int n = bn0 + q;
                int ntile = n >> 3;
                uint32_t h, l;
                split_pair(f0[q], f1[q], h, l);
                int lin = ntile * 64 + (n & 7) * 8 + bkt;
                int sw = lin ^ ((ntile & 15) << 1);
                sb[S_BHI + sw] = h;
                sb[S_BLO + sw] = l;
            }
        }
    };

    LOAD_TILE(0);
    STORE_TILE(0);
    __syncthreads();

    int cur = 0;
    for (int t = 0; t < nt; t++) {
        const bool more = (t + 1 < nt);
        if (more) LOAD_TILE(t + 1);

        const uint32_t* sb = smem + cur * S_BUF;

        uint32_t bh[4][2], bl[4][2];
#pragma unroll
        for (int ni = 0; ni < 4; ni++) {
            int ntile = warp_n * 4 + ni;
            int lin = ntile * 64 + lane * 2;
            int sw = lin ^ ((ntile & 15) << 1);
            uint2 h = *reinterpret_cast<const uint2*>(sb + S_BHI + sw);
            uint2 l = *reinterpret_cast<const uint2*>(sb + S_BLO + sw);
            bh[ni][0] = h.x; bh[ni][1] = h.y;
            bl[ni][0] = l.x; bl[ni][1] = l.y;
        }

#pragma unroll
        for (int mi = 0; mi < 2; mi++) {
            int mtile = warp_m * 2 + mi;
            int lin = mtile * 128 + lane * 4;
            int sw = a_swz(lin);
            uint4 h4 = *reinterpret_cast<const uint4*>(sb + S_AHI + sw);
            uint4 l4 = *reinterpret_cast<const uint4*>(sb + S_ALO + sw);
            uint32_t ah[4] = {h4.x, h4.y, h4.z, h4.w};
            uint32_t al[4] = {l4.x, l4.y, l4.z, l4.w};
#pragma unroll
            for (int ni = 0; ni < 4; ni++)
                mma_bf16(c[mi][ni], ah, bh[ni]);
#pragma unroll
            for (int ni = 0; ni < 4; ni++)
                mma_bf16(c[mi][ni], ah, bl[ni]);
#pragma unroll
            for (int ni = 0; ni < 4; ni++)
                mma_bf16(c[mi][ni], al, bh[ni]);
        }

        if (more) {
            STORE_TILE(cur ^ 1);
            __syncthreads();
            cur ^= 1;
        }
    }

    // ---- epilogue ----
    const int gid = lane >> 2;
    const int tig = lane & 3;
#pragma unroll
    for (int mi = 0; mi < 2; mi++) {
#pragma unroll
        for (int half = 0; half < 2; half++) {
            int gm = bm + warp_m * 32 + mi * 16 + gid + half * 8;
            if (gm >= M) continue;
            float dd = 0.f;
            if (C2) { float dv = dinv[gm]; dd = dv * dv; }
#pragma unroll
            for (int ni = 0; ni < 4; ni++) {
                int gn = bn + warp_n * 32 + ni * 8 + tig * 2;
                float v0 = c[mi][ni][half * 2 + 0];
                float v1 = c[mi][ni][half * 2 + 1];
                if (C2) {
                    *reinterpret_cast<float2*>(C + (size_t)gm * N + gn) =
                        make_float2(v0, v1);
                    float b0 = bias[gn], b1 = bias[gn + 1];
                    *reinterpret_cast<float2*>(C2 + (size_t)gm * N + gn) =
                        make_float2(b0 + dd * v0, b1 + dd * v1);
                } else {
                    if (bias) { v0 += bias[gn]; v1 += bias[gn + 1]; }
                    if (reluOut) { v0 = fmaxf(v0, 0.f); v1 = fmaxf(v1, 0.f); }
                    *reinterpret_cast<float2*>(C + (size_t)gm * N + gn) =
                        make_float2(v0, v1);
                }
            }
        }
    }
}

// ---------------- segment pool (sum + max), values >= 0 -----------
__global__ void segpool_kernel(const float* __restrict__ in,
                               const int* __restrict__ seg,
                               int M, int F,
                               float* __restrict__ outSum,
                               float* __restrict__ outMax,
                               int ldOut, int nodesPerBlock) {
    int f = threadIdx.x;
    int n0 = blockIdx.x * nodesPerBlock;
    int n1 = n0 + nodesPerBlock;
    if (n1 > M) n1 = M;
    if (n0 >= n1) return;
    int cur = seg[n0];
    float s = 0.f, mx = 0.f;
    for (int n = n0; n < n1; n++) {
        int sg = seg[n];
        if (sg != cur) {
            atomicAdd(&outSum[cur * ldOut + f], s);
            atomicMax((int*)&outMax[cur * ldOut + f], __float_as_int(mx));
            s = 0.f; mx = 0.f; cur = sg;
        }
        float v = in[(size_t)n * F + f];
        s += v;
        mx = fmaxf(mx, v);
    }
    atomicAdd(&outSum[cur * ldOut + f], s);
    atomicMax((int*)&outMax[cur * ldOut + f], __float_as_int(mx));
}

// Fused dual pool over level-0 nodes: batch pool into z, cover pool into h1cat.
__global__ void dualpool_kernel(const float* __restrict__ h,
                                const int* __restrict__ batch,
                                const int* __restrict__ nodeIdx,
                                const int* __restrict__ clus,
                                int M,
                                float* __restrict__ zSum, float* __restrict__ zMax,
                                float* __restrict__ cSum, float* __restrict__ cMax,
                                int nodesPerBlock) {
    int f = threadIdx.x;
    int n0 = blockIdx.x * nodesPerBlock;
    int n1 = n0 + nodesPerBlock;
    if (n1 > M) n1 = M;
    if (n0 >= n1) return;
    int curB = batch[n0], curC = clus[n0];
    float sB = 0.f, mB = 0.f, sC = 0.f, mC = 0.f;
    for (int n = n0; n < n1; n++) {
        int b = batch[n];
        int cl = clus[n];
        if (b != curB) {
            atomicAdd(&zSum[curB * (4 * HC) + f], sB);
            atomicMax((int*)&zMax[curB * (4 * HC) + f], __float_as_int(mB));
            sB = 0.f; mB = 0.f; curB = b;
        }
        if (cl != curC) {
            atomicAdd(&cSum[curC * (2 * HC) + f], sC);
            atomicMax((int*)&cMax[curC * (2 * HC) + f], __float_as_int(mC));
            sC = 0.f; mC = 0.f; curC = cl;
        }
        float v = h[(size_t)n * HC + f];
        sB += v; mB = fmaxf(mB, v);
        int ni = nodeIdx[n];
        float vc = (ni == n) ? v : h[(size_t)ni * HC + f];
        sC += vc; mC = fmaxf(mC, vc);
    }
    atomicAdd(&zSum[curB * (4 * HC) + f], sB);
    atomicMax((int*)&zMax[curB * (4 * HC) + f], __float_as_int(mB));
    atomicAdd(&cSum[curC * (2 * HC) + f], sC);
    atomicMax((int*)&cMax[curC * (2 * HC) + f], __float_as_int(mC));
}

// ---------------- head ----------------
__global__ void head_kernel(const float* __restrict__ z,
                            const float* __restrict__ gamma,
                            const float* __restrict__ beta,
                            const float* __restrict__ mean,
                            const float* __restrict__ var,
                            const float* __restrict__ W1,
                            const float* __restrict__ b1,
                            const float* __restrict__ W2,
                            const float* __restrict__ b2,
                            float* __restrict__ out) {
    __shared__ float zn[4 * HC];
    __shared__ float s1[HC];
    __shared__ float logits[16];
    int b = blockIdx.x;
    int t = threadIdx.x;
    for (int k = t; k < 4 * HC; k += 256) {
        float v = z[b * 4 * HC + k];
        zn[k] = (v - mean[k]) * rsqrtf(var[k] + 1e-5f) * gamma[k] + beta[k];
    }
    __syncthreads();
    float acc = b1[t];
    for (int k = 0; k < 4 * HC; k++) acc += zn[k] * W1[k * HC + t];
    s1[t] = fmaxf(acc, 0.f);
    __syncthreads();
    if (t < 10) {
        float a2 = b2[t];
        for (int k = 0; k < HC; k++) a2 += s1[k] * W2[k * 10 + t];
        logits[t] = a2;
    }
    __syncthreads();
    if (t == 0) {
        float mx = logits[0];
        for (int c = 1; c < 10; c++) mx = fmaxf(mx, logits[c]);
        float e[10], sum = 0.f;
        for (int c = 0; c < 10; c++) { e[c] = expf(logits[c] - mx); sum += e[c]; }
        float inv = 1.f / sum;
        for (int c = 0; c < 10; c++) out[b * 10 + c] = e[c] * inv;
    }
}

// ---------------- orchestration ----------------
static inline int ceil_div(int a, int b) { return (a + b - 1) / b; }
#define GEMM_SMEM (2 * S_BUF * (int)sizeof(uint32_t))

extern "C" void kernel_launch(void* const* d_in, const int* in_sizes, int n_in,
                              void* d_out, int out_size) {
    const float* x      = (const float*)d_in[0];
    const int*   ei0    = (const int*)d_in[1];
    const float* ew0    = (const float*)d_in[2];
    const int*   batch0 = (const int*)d_in[3];
    const int*   cover  = (const int*)d_in[4];
    const int*   ei1    = (const int*)d_in[5];
    const float* ew1    = (const float*)d_in[6];
    const int*   batch1 = (const int*)d_in[7];
    const float* W_in0  = (const float*)d_in[8];
    const float* b_in0  = (const float*)d_in[9];
    const float* W_in1  = (const float*)d_in[10];
    const float* b_in1  = (const float*)d_in[11];
    const float* W_jk_in= (const float*)d_in[12];
    const float* b_jk_in= (const float*)d_in[13];
    const float* W_b0   = (const float*)d_in[14];
    const float* b_b0   = (const float*)d_in[15];
    const float* W_b1   = (const float*)d_in[16];
    const float* b_b1   = (const float*)d_in[17];
    const float* W_jk_b = (const float*)d_in[18];
    const float* b_jk_b = (const float*)d_in[19];
    const float* bn_g   = (const float*)d_in[20];
    const float* bn_b   = (const float*)d_in[21];
    const float* bn_m   = (const float*)d_in[22];
    const float* bn_v   = (const float*)d_in[23];
    const float* W_lin1 = (const float*)d_in[24];
    const float* b_lin1 = (const float*)d_in[25];
    const float* W_lin2 = (const float*)d_in[26];
    const float* b_lin2 = (const float*)d_in[27];
    float* out = (float*)d_out;

    const int N0 = in_sizes[3];
    const int E0 = in_sizes[2];
    const int N1 = in_sizes[7];
    const int E1 = in_sizes[6];
    const int H = HC;

    const int* row0 = ei0;
    const int* col0 = ei0 + E0;
    const int* nodeC = cover;
    const int* clusC = cover + N0;
    const int* row1 = ei1;
    const int* col1 = ei1 + E1;

    float *xw, *x1, *x2, *h, *dinv0, *coef0, *h1cat, *yw, *y1, *y2, *hb, *dinv1, *coef1, *z;
    cudaGetSymbolAddress((void**)&xw, g_xw);
    cudaGetSymbolAddress((void**)&x1, g_x1);
    cudaGetSymbolAddress((void**)&x2, g_x2);
    cudaGetSymbolAddress((void**)&h,  g_h);
    cudaGetSymbolAddress((void**)&dinv0, g_dinv0);
    cudaGetSymbolAddress((void**)&coef0, g_coef0);
    cudaGetSymbolAddress((void**)&h1cat, g_h1cat);
    cudaGetSymbolAddress((void**)&yw, g_yw);
    cudaGetSymbolAddress((void**)&y1, g_y1);
    cudaGetSymbolAddress((void**)&y2, g_y2);
    cudaGetSymbolAddress((void**)&hb, g_hb);
    cudaGetSymbolAddress((void**)&dinv1, g_dinv1);
    cudaGetSymbolAddress((void**)&coef1, g_coef1);
    cudaGetSymbolAddress((void**)&z,  g_z);

    int *cnt0, *start0, *cur0, *srow0, *cnt1, *start1, *cur1, *srow1;
    float *scoef0, *scoef1;
    cudaGetSymbolAddress((void**)&cnt0, g_cnt0);
    cudaGetSymbolAddress((void**)&start0, g_start0);
    cudaGetSymbolAddress((void**)&cur0, g_cur0);
    cudaGetSymbolAddress((void**)&srow0, g_srow0);
    cudaGetSymbolAddress((void**)&scoef0, g_scoef0);
    cudaGetSymbolAddress((void**)&cnt1, g_cnt1);
    cudaGetSymbolAddress((void**)&start1, g_start1);
    cudaGetSymbolAddress((void**)&cur1, g_cur1);
    cudaGetSymbolAddress((void**)&srow1, g_srow1);
    cudaGetSymbolAddress((void**)&scoef1, g_scoef1);

    cudaFuncSetAttribute(gemm_tc_kernel,
                         cudaFuncAttributeMaxDynamicSharedMemorySize, GEMM_SMEM);

    dim3 gemmBlk(256);
    dim3 g0(H / GBN, ceil_div(N0, GBM));
    dim3 g1(H / GBN, ceil_div(N1, GBM));

    // ncu (-s 5 -c 1 incl. 2 harness launches) profiles MY 4th launch (the big GEMM).
    fill_kernel<<<ceil_div(N0, 256), 256>>>(dinv0, N0, 1.f);                 // 1
    deg_accum_kernel<<<ceil_div(E0, 256), 256>>>(col0, ew0, dinv0, E0);      // 2
    finalize_dinv_kernel<<<ceil_div(N0, 256), 256>>>(dinv0, N0);             // 3

    // ---- level 0: GCN 1 GEMM (fused: xw=x@W, x1=b+dinv^2*xw) ----
    gemm_tc_kernel<<<g0, gemmBlk, GEMM_SMEM>>>(x, x, FC, FC, W_in0, b_in0, xw, x1, dinv0,
                                               N0, H, 0, 0);                 // 4 (profiled)

    // ---- level-0 CSR build ----
    edge_coef_kernel<<<ceil_div(E0, 256), 256>>>(row0, col0, ew0, dinv0, coef0, E0);
    filli_kernel<<<ceil_div(N0, 256), 256>>>(cnt0, N0, 0);
    count_kernel<<<ceil_div(E0, 256), 256>>>(col0, cnt0, E0);
    scan_kernel<<<1, 1024>>>(cnt0, start0, cur0, N0);
    emit_kernel<<<ceil_div(E0, 256), 256>>>(row0, col0, coef0, cur0, srow0, scoef0, E0);

    // ---- level 0: GCN 1 aggregate ----
    gcn_gather_csr<<<ceil_div(N0, 4), 256>>>(xw, srow0, scoef0, start0, x1, N0);

    // level-1 prep (independent)
    fill_kernel<<<ceil_div(N1, 256), 256>>>(dinv1, N1, 1.f);
    deg_accum_kernel<<<ceil_div(E1, 256), 256>>>(col1, ew1, dinv1, E1);
    finalize_dinv_kernel<<<ceil_div(N1, 256), 256>>>(dinv1, N1);
    edge_coef_kernel<<<ceil_div(E1, 256), 256>>>(row1, col1, ew1, dinv1, coef1, E1);
    filli_kernel<<<ceil_div(N1, 256), 256>>>(cnt1, N1, 0);
    count_kernel<<<ceil_div(E1, 256), 256>>>(col1, cnt1, E1);
    scan_kernel<<<1, 1024>>>(cnt1, start1, cur1, N1);
    emit_kernel<<<ceil_div(E1, 256), 256>>>(row1, col1, coef1, cur1, srow1, scoef1, E1);
    fill_kernel<<<ceil_div(BC * 4 * H, 256), 256>>>(z, BC * 4 * H, 0.f);
    fill_kernel<<<ceil_div(N1 * 2 * H, 256), 256>>>(h1cat, N1 * 2 * H, 0.f);

    // ---- level 0: GCN 2 ----
    gemm_tc_kernel<<<g0, gemmBlk, GEMM_SMEM>>>(x1, x1, H, H, W_in1, b_in1, xw, x2, dinv0,
                                               N0, H, 1, 0);
    gcn_gather_csr<<<ceil_div(N0, 4), 256>>>(xw, srow0, scoef0, start0, x2, N0);

    // ---- level 0: JK cat + linear + relu ----
    gemm_tc_kernel<<<g0, gemmBlk, GEMM_SMEM>>>(x1, x2, H, 2 * H, W_jk_in, b_jk_in, h,
                                               NULL, NULL, N0, H, 1, 1);

    // ---- fused level-0 pools (batch -> z, cover -> h1cat) ----
    dualpool_kernel<<<ceil_div(N0, 128), 256>>>(h, batch0, nodeC, clusC, N0,
                                                z + 0, z + H,
                                                h1cat + 0, h1cat + H, 128);

    // ---- level 1: GCN 1 ----
    gemm_tc_kernel<<<g1, gemmBlk, GEMM_SMEM>>>(h1cat, h1cat, 2 * H, 2 * H, W_b0, b_b0,
                                               yw, y1, dinv1, N1, H, 0, 0);
    gcn_gather_csr<<<ceil_div(N1, 4), 256>>>(yw, srow1, scoef1, start1, y1, N1);

    // ---- level 1: GCN 2 ----
    gemm_tc_kernel<<<g1, gemmBlk, GEMM_SMEM>>>(y1, y1, H, H, W_b1, b_b1, yw, y2, dinv1,
                                               N1, H, 1, 0);
    gcn_gather_csr<<<ceil_div(N1, 4), 256>>>(yw, srow1, scoef1, start1, y2, N1);

    // ---- level 1: JK ----
    gemm_tc_kernel<<<g1, gemmBlk, GEMM_SMEM>>>(y1, y2, H, 2 * H, W_jk_b, b_jk_b, hb,
                                               NULL, NULL, N1, H, 1, 1);

    // ---- level-1 batch pool ----
    segpool_kernel<<<ceil_div(N1, 128), 256>>>(hb, batch1, N1, H,
                                               z + 2 * H, z + 3 * H, 4 * H, 128);

    // ---- head ----
    head_kernel<<<BC, 256>>>(z, bn_g, bn_b, bn_m, bn_v,
                             W_lin1, b_lin1, W_lin2, b_lin2, out);
}

// round 15
// speedup vs baseline: 1.1664x; 1.1664x over previous
#include <cuda_runtime.h>
#include <math.h>
#include <stdint.h>

#define N0C 50000
#define E0C 800000
#define N1C 10000
#define E1C 160000
#define FC  128
#define HC  256
#define BC  64

// ---------------- static scratch ----------------
__device__ float g_xw [N0C * HC];
__device__ float g_x1 [N0C * HC];
__device__ float g_x2 [N0C * HC];
__device__ float g_h  [N0C * HC];
__device__ float g_dinv0[N0C];
__device__ float g_coef0[E0C];

__device__ float g_h1cat[N1C * 2 * HC];
__device__ float g_yw [N1C * HC];
__device__ float g_y1 [N1C * HC];
__device__ float g_y2 [N1C * HC];
__device__ float g_hb [N1C * HC];
__device__ float g_dinv1[N1C];
__device__ float g_coef1[E1C];

__device__ float g_z [BC * 4 * HC];

// CSR scratch
__device__ int   g_cnt0[N0C];
__device__ int   g_start0[N0C + 1];
__device__ int   g_cur0[N0C];
__device__ int   g_srow0[E0C];
__device__ float g_scoef0[E0C];
__device__ int   g_cnt1[N1C];
__device__ int   g_start1[N1C + 1];
__device__ int   g_cur1[N1C];
__device__ int   g_srow1[E1C];
__device__ float g_scoef1[E1C];

// ---------------- utility kernels ----------------
__global__ void fill_kernel(float* p, int n, float v) {
    int i = blockIdx.x * blockDim.x + threadIdx.x;
    if (i < n) p[i] = v;
}

__global__ void filli_kernel(int* p, int n, int v) {
    int i = blockIdx.x * blockDim.x + threadIdx.x;
    if (i < n) p[i] = v;
}

__global__ void deg_accum_kernel(const int* __restrict__ col,
                                 const float* __restrict__ ew,
                                 float* __restrict__ deg, int E) {
    int e = blockIdx.x * blockDim.x + threadIdx.x;
    if (e < E) atomicAdd(&deg[col[e]], ew[e]);
}

__global__ void finalize_dinv_kernel(float* deg, int n) {
    int i = blockIdx.x * blockDim.x + threadIdx.x;
    if (i < n) {
        float d = deg[i];
        deg[i] = (d > 0.f) ? rsqrtf(d) : 0.f;
    }
}

__global__ void edge_coef_kernel(const int* __restrict__ row,
                                 const int* __restrict__ col,
                                 const float* __restrict__ ew,
                                 const float* __restrict__ dinv,
                                 float* __restrict__ coef, int E) {
    int e = blockIdx.x * blockDim.x + threadIdx.x;
    if (e < E) coef[e] = dinv[row[e]] * ew[e] * dinv[col[e]];
}

// ---------------- CSR build ----------------
__global__ void count_kernel(const int* __restrict__ col,
                             int* __restrict__ cnt, int E) {
    int e = blockIdx.x * blockDim.x + threadIdx.x;
    if (e < E) atomicAdd(&cnt[col[e]], 1);
}

__global__ void scan_kernel(const int* __restrict__ cnt,
                            int* __restrict__ start,
                            int* __restrict__ cursor, int n) {
    __shared__ int part[1024];
    int tid = threadIdx.x;
    int chunk = (n + 1023) / 1024;
    int base = tid * chunk;
    int s = 0;
    for (int i = 0; i < chunk; i++) {
        int idx = base + i;
        if (idx < n) s += cnt[idx];
    }
    part[tid] = s;
    __syncthreads();
    for (int off = 1; off < 1024; off <<= 1) {
        int v = (tid >= off) ? part[tid - off] : 0;
        __syncthreads();
        part[tid] += v;
        __syncthreads();
    }
    int run = (tid == 0) ? 0 : part[tid - 1];
    for (int i = 0; i < chunk; i++) {
        int idx = base + i;
        if (idx < n) {
            start[idx] = run;
            cursor[idx] = run;
            run += cnt[idx];
        }
    }
    if (tid == 1023) start[n] = run;
}

__global__ void emit_kernel(const int* __restrict__ row,
                            const int* __restrict__ col,
                            const float* __restrict__ coef,
                            int* __restrict__ cursor,
                            int* __restrict__ srow,
                            float* __restrict__ scoef, int E) {
    int e = blockIdx.x * blockDim.x + threadIdx.x;
    if (e < E) {
        int c = col[e];
        int p = atomicAdd(&cursor[c], 1);
        srow[p] = row[e];
        scoef[p] = coef[e];
    }
}

// Gather-by-destination: out[c,:] += sum_e coef*xw[row,:]. No output atomics.
__global__ void gcn_gather_csr(const float* __restrict__ xw,
                               const int* __restrict__ srow,
                               const float* __restrict__ scoef,
                               const int* __restrict__ start,
                               float* __restrict__ out, int N) {
    int f4 = threadIdx.x & 63;
    int slot = threadIdx.x >> 6;
    int c = blockIdx.x * 4 + slot;
    if (c >= N) return;
    int p  = start[c];
    int pe = start[c + 1];
    float4 acc = make_float4(0.f, 0.f, 0.f, 0.f);
    for (; p + 1 < pe; p += 2) {
        int r0 = srow[p],     r1 = srow[p + 1];
        float c0 = scoef[p],  c1 = scoef[p + 1];
        float4 v0 = *reinterpret_cast<const float4*>(xw + (size_t)r0 * HC + f4 * 4);
        float4 v1 = *reinterpret_cast<const float4*>(xw + (size_t)r1 * HC + f4 * 4);
        acc.x += c0 * v0.x + c1 * v1.x;
        acc.y += c0 * v0.y + c1 * v1.y;
        acc.z += c0 * v0.z + c1 * v1.z;
        acc.w += c0 * v0.w + c1 * v1.w;
    }
    if (p < pe) {
        int r = srow[p];
        float cf = scoef[p];
        float4 v = *reinterpret_cast<const float4*>(xw + (size_t)r * HC + f4 * 4);
        acc.x += cf * v.x; acc.y += cf * v.y;
        acc.z += cf * v.z; acc.w += cf * v.w;
    }
    float4* dst = reinterpret_cast<float4*>(out + (size_t)c * HC + f4 * 4);
    float4 cur = *dst;
    cur.x += acc.x; cur.y += acc.y; cur.z += acc.z; cur.w += acc.w;
    *dst = cur;
}

// ---------------- bf16 2-term tensor-core GEMM (A hi/lo, B single bf16) ----
// 128x128 tile, 2 CTAs/SM (R13 config). C = a*bh with a exact (ah+al).
#define GBM 128
#define GBN 128
#define S_AHI 0
#define S_ALO 1024
#define S_BHI 2048
#define S_BUF 3072

__device__ __forceinline__ void split_pair(float fx, float fy,
                                           uint32_t& hi, uint32_t& lo) {
    asm("cvt.rn.bf16x2.f32 %0, %1, %2;" : "=r"(hi) : "f"(fy), "f"(fx));
    float hx = __uint_as_float(hi << 16);
    float hy = __uint_as_float(hi & 0xFFFF0000u);
    float rx = fx - hx;
    float ry = fy - hy;
    asm("cvt.rn.bf16x2.f32 %0, %1, %2;" : "=r"(lo) : "f"(ry), "f"(rx));
}

__device__ __forceinline__ uint32_t pack_bf16(float fx, float fy) {
    uint32_t h;
    asm("cvt.rn.bf16x2.f32 %0, %1, %2;" : "=r"(h) : "f"(fy), "f"(fx));
    return h;
}

__device__ __forceinline__ void mma_bf16(float* c, const uint32_t* a, const uint32_t* b) {
    asm volatile(
        "mma.sync.aligned.m16n8k16.row.col.f32.bf16.bf16.f32 "
        "{%0,%1,%2,%3}, {%4,%5,%6,%7}, {%8,%9}, {%0,%1,%2,%3};"
        : "+f"(c[0]), "+f"(c[1]), "+f"(c[2]), "+f"(c[3])
        : "r"(a[0]), "r"(a[1]), "r"(a[2]), "r"(a[3]), "r"(b[0]), "r"(b[1]));
}

__device__ __forceinline__ int a_swz(int lin) {
    return lin ^ (((lin >> 5) & 3) << 2);
}

__global__ __launch_bounds__(256, 2)
void gemm_tc_kernel(const float* __restrict__ A1,
                    const float* __restrict__ A2,
                    int K1, int K,
                    const float* __restrict__ W,
                    const float* __restrict__ bias,
                    float* __restrict__ C,
                    float* __restrict__ C2,
                    const float* __restrict__ dinv,
                    int M, int N,
                    int reluIn, int reluOut) {
    extern __shared__ uint32_t smem[];

    const int tid  = threadIdx.x;
    const int lane = tid & 31;
    const int warp = tid >> 5;
    const int warp_m = warp & 1;
    const int warp_n = warp >> 1;
    const int bm = blockIdx.y * GBM;
    const int bn = blockIdx.x * GBN;
    const int K2 = K - K1;

    const int am     = tid >> 1;
    const int ak0    = (tid & 1) * 8;
    const int amtile = am >> 4;
    const int ar     = am & 15;
    const int abase  = amtile * 128 + (ar & 7) * 16 + (ar >> 3);

    const int bkp  = tid >> 5;
    const int bn0  = (tid & 31) * 4;
    const int bkt  = (bkp & 3) * 2 + (bkp >> 2);

    float c[4][4][4];
#pragma unroll
    for (int mi = 0; mi < 4; mi++)
#pragma unroll
        for (int ni = 0; ni < 4; ni++)
#pragma unroll
            for (int q = 0; q < 4; q++) c[mi][ni][q] = 0.f;

    const int nt = K / 16;

    float4 va[2], vw[2];
    auto LOAD_TILE = [&](int t) {
        const int gk0 = t * 16;
#pragma unroll
        for (int i = 0; i < 2; i++) {
            int gk = gk0 + ak0 + i * 4;
            int gm = bm + am;
            float4 v = make_float4(0.f, 0.f, 0.f, 0.f);
            if (gm < M) {
                const float* src = (gk < K1) ? (A1 + (size_t)gm * K1 + gk)
                                             : (A2 + (size_t)gm * K2 + (gk - K1));
                v = *reinterpret_cast<const float4*>(src);
            }
            if (reluIn) {
                v.x = fmaxf(v.x, 0.f); v.y = fmaxf(v.y, 0.f);
                v.z = fmaxf(v.z, 0.f); v.w = fmaxf(v.w, 0.f);
            }
            va[i] = v;
        }
        int r0 = gk0 + 2 * bkp;
        vw[0] = *reinterpret_cast<const float4*>(W + (size_t)r0 * N + bn + bn0);
        vw[1] = *reinterpret_cast<const float4*>(W + (size_t)(r0 + 1) * N + bn + bn0);
    };

    auto STORE_TILE = [&](int buf) {
        uint32_t* sb = smem + buf * S_BUF;
#pragma unroll
        for (int i = 0; i < 2; i++) {
            int p = (ak0 >> 1) + 2 * i;
            uint32_t h, l;
            split_pair(va[i].x, va[i].y, h, l);
            int lin = abase + (p & 3) * 4 + (p >> 2) * 2;
            int sw = a_swz(lin);
            sb[S_AHI + sw] = h;
            sb[S_ALO + sw] = l;
            split_pair(va[i].z, va[i].w, h, l);
            p++;
            lin = abase + (p & 3) * 4 + (p >> 2) * 2;
            sw = a_swz(lin);
            sb[S_AHI + sw] = h;
            sb[S_ALO + sw] = l;
        }
        float f0[4] = {vw[0].x, vw[0].y, vw[0].z, vw[0].w};
        float f1[4] = {vw[1].x, vw[1].y, vw[1].z, vw[1].w};
#pragma unroll
        for (int q = 0; q < 4; q++) {
            int n = bn0 + q;
            int ntile = n >> 3;
            uint32_t h = pack_bf16(f0[q], f1[q]);
            int lin = ntile * 64 + (n & 7) * 8 + bkt;
            int sw = lin ^ ((ntile & 15) << 1);
            sb[S_BHI + sw] = h;
        }
    };

    LOAD_TILE(0);
    STORE_TILE(0);
    __syncthreads();

    int cur = 0;
    for (int t = 0; t < nt; t++) {
        const bool more = (t + 1 < nt);
        if (more) LOAD_TILE(t + 1);

        const uint32_t* sb = smem + cur * S_BUF;

        uint32_t bh[4][2];
#pragma unroll
        for (int ni = 0; ni < 4; ni++) {
            int ntile = warp_n * 4 + ni;
            int lin = ntile * 64 + lane * 2;
            int sw = lin ^ ((ntile & 15) << 1);
            uint2 h = *reinterpret_cast<const uint2*>(sb + S_BHI + sw);
            bh[ni][0] = h.x; bh[ni][1] = h.y;
        }

#pragma unroll
        for (int mi = 0; mi < 4; mi++) {
            int mtile = warp_m * 4 + mi;
            int lin = mtile * 128 + lane * 4;
            int sw = a_swz(lin);
            uint4 h4 = *reinterpret_cast<const uint4*>(sb + S_AHI + sw);
            uint4 l4 = *reinterpret_cast<const uint4*>(sb + S_ALO + sw);
            uint32_t ah[4] = {h4.x, h4.y, h4.z, h4.w};
            uint32_t al[4] = {l4.x, l4.y, l4.z, l4.w};
#pragma unroll
            for (int ni = 0; ni < 4; ni++)
                mma_bf16(c[mi][ni], ah, bh[ni]);
#pragma unroll
            for (int ni = 0; ni < 4; ni++)
                mma_bf16(c[mi][ni], al, bh[ni]);
        }

        if (more) {
            STORE_TILE(cur ^ 1);
            __syncthreads();
            cur ^= 1;
        }
    }

    // ---- epilogue ----
    const int gid = lane >> 2;
    const int tig = lane & 3;
#pragma unroll
    for (int mi = 0; mi < 4; mi++) {
#pragma unroll
        for (int half = 0; half < 2; half++) {
            int gm = bm + warp_m * 64 + mi * 16 + gid + half * 8;
            if (gm >= M) continue;
            float dd = 0.f;
            if (C2) { float dv = dinv[gm]; dd = dv * dv; }
#pragma unroll
            for (int ni = 0; ni < 4; ni++) {
                int gn = bn + warp_n * 32 + ni * 8 + tig * 2;
                float v0 = c[mi][ni][half * 2 + 0];
                float v1 = c[mi][ni][half * 2 + 1];
                if (C2) {
                    *reinterpret_cast<float2*>(C + (size_t)gm * N + gn) =
                        make_float2(v0, v1);
                    float b0 = bias[gn], b1 = bias[gn + 1];
                    *reinterpret_cast<float2*>(C2 + (size_t)gm * N + gn) =
                        make_float2(b0 + dd * v0, b1 + dd * v1);
                } else {
                    if (bias) { v0 += bias[gn]; v1 += bias[gn + 1]; }
                    if (reluOut) { v0 = fmaxf(v0, 0.f); v1 = fmaxf(v1, 0.f); }
                    *reinterpret_cast<float2*>(C + (size_t)gm * N + gn) =
                        make_float2(v0, v1);
                }
            }
        }
    }
}

// ---------------- segment pool (sum + max), values >= 0 -----------
__global__ void segpool_kernel(const float* __restrict__ in,
                               const int* __restrict__ seg,
                               int M, int F,
                               float* __restrict__ outSum,
                               float* __restrict__ outMax,
                               int ldOut, int nodesPerBlock) {
    int f = threadIdx.x;
    int n0 = blockIdx.x * nodesPerBlock;
    int n1 = n0 + nodesPerBlock;
    if (n1 > M) n1 = M;
    if (n0 >= n1) return;
    int cur = seg[n0];
    float s = 0.f, mx = 0.f;
    for (int n = n0; n < n1; n++) {
        int sg = seg[n];
        if (sg != cur) {
            atomicAdd(&outSum[cur * ldOut + f], s);
            atomicMax((int*)&outMax[cur * ldOut + f], __float_as_int(mx));
            s = 0.f; mx = 0.f; cur = sg;
        }
        float v = in[(size_t)n * F + f];
        s += v;
        mx = fmaxf(mx, v);
    }
    atomicAdd(&outSum[cur * ldOut + f], s);
    atomicMax((int*)&outMax[cur * ldOut + f], __float_as_int(mx));
}

// Fused dual pool over level-0 nodes: batch pool into z, cover pool into h1cat.
__global__ void dualpool_kernel(const float* __restrict__ h,
                                const int* __restrict__ batch,
                                const int* __restrict__ nodeIdx,
                                const int* __restrict__ clus,
                                int M,
                                float* __restrict__ zSum, float* __restrict__ zMax,
                                float* __restrict__ cSum, float* __restrict__ cMax,
                                int nodesPerBlock) {
    int f = threadIdx.x;
    int n0 = blockIdx.x * nodesPerBlock;
    int n1 = n0 + nodesPerBlock;
    if (n1 > M) n1 = M;
    if (n0 >= n1) return;
    int curB = batch[n0], curC = clus[n0];
    float sB = 0.f, mB = 0.f, sC = 0.f, mC = 0.f;
    for (int n = n0; n < n1; n++) {
        int b = batch[n];
        int cl = clus[n];
        if (b != curB) {
            atomicAdd(&zSum[curB * (4 * HC) + f], sB);
            atomicMax((int*)&zMax[curB * (4 * HC) + f], __float_as_int(mB));
            sB = 0.f; mB = 0.f; curB = b;
        }
        if (cl != curC) {
            atomicAdd(&cSum[curC * (2 * HC) + f], sC);
            atomicMax((int*)&cMax[curC * (2 * HC) + f], __float_as_int(mC));
            sC = 0.f; mC = 0.f; curC = cl;
        }
        float v = h[(size_t)n * HC + f];
        sB += v; mB = fmaxf(mB, v);
        int ni = nodeIdx[n];
        float vc = (ni == n) ? v : h[(size_t)ni * HC + f];
        sC += vc; mC = fmaxf(mC, vc);
    }
    atomicAdd(&zSum[curB * (4 * HC) + f], sB);
    atomicMax((int*)&zMax[curB * (4 * HC) + f], __float_as_int(mB));
    atomicAdd(&cSum[curC * (2 * HC) + f], sC);
    atomicMax((int*)&cMax[curC * (2 * HC) + f], __float_as_int(mC));
}

// ---------------- head ----------------
__global__ void head_kernel(const float* __restrict__ z,
                            const float* __restrict__ gamma,
                            const float* __restrict__ beta,
                            const float* __restrict__ mean,
                            const float* __restrict__ var,
                            const float* __restrict__ W1,
                            const float* __restrict__ b1,
                            const float* __restrict__ W2,
                            const float* __restrict__ b2,
                            float* __restrict__ out) {
    __shared__ float zn[4 * HC];
    __shared__ float s1[HC];
    __shared__ float logits[16];
    int b = blockIdx.x;
    int t = threadIdx.x;
    for (int k = t; k < 4 * HC; k += 256) {
        float v = z[b * 4 * HC + k];
        zn[k] = (v - mean[k]) * rsqrtf(var[k] + 1e-5f) * gamma[k] + beta[k];
    }
    __syncthreads();
    float acc = b1[t];
    for (int k = 0; k < 4 * HC; k++) acc += zn[k] * W1[k * HC + t];
    s1[t] = fmaxf(acc, 0.f);
    __syncthreads();
    if (t < 10) {
        float a2 = b2[t];
        for (int k = 0; k < HC; k++) a2 += s1[k] * W2[k * 10 + t];
        logits[t] = a2;
    }
    __syncthreads();
    if (t == 0) {
        float mx = logits[0];
        for (int c = 1; c < 10; c++) mx = fmaxf(mx, logits[c]);
        float e[10], sum = 0.f;
        for (int c = 0; c < 10; c++) { e[c] = expf(logits[c] - mx); sum += e[c]; }
        float inv = 1.f / sum;
        for (int c = 0; c < 10; c++) out[b * 10 + c] = e[c] * inv;
    }
}

// ---------------- orchestration ----------------
static inline int ceil_div(int a, int b) { return (a + b - 1) / b; }
#define GEMM_SMEM (2 * S_BUF * (int)sizeof(uint32_t))

extern "C" void kernel_launch(void* const* d_in, const int* in_sizes, int n_in,
                              void* d_out, int out_size) {
    const float* x      = (const float*)d_in[0];
    const int*   ei0    = (const int*)d_in[1];
    const float* ew0    = (const float*)d_in[2];
    const int*   batch0 = (const int*)d_in[3];
    const int*   cover  = (const int*)d_in[4];
    const int*   ei1    = (const int*)d_in[5];
    const float* ew1    = (const float*)d_in[6];
    const int*   batch1 = (const int*)d_in[7];
    const float* W_in0  = (const float*)d_in[8];
    const float* b_in0  = (const float*)d_in[9];
    const float* W_in1  = (const float*)d_in[10];
    const float* b_in1  = (const float*)d_in[11];
    const float* W_jk_in= (const float*)d_in[12];
    const float* b_jk_in= (const float*)d_in[13];
    const float* W_b0   = (const float*)d_in[14];
    const float* b_b0   = (const float*)d_in[15];
    const float* W_b1   = (const float*)d_in[16];
    const float* b_b1   = (const float*)d_in[17];
    const float* W_jk_b = (const float*)d_in[18];
    const float* b_jk_b = (const float*)d_in[19];
    const float* bn_g   = (const float*)d_in[20];
    const float* bn_b   = (const float*)d_in[21];
    const float* bn_m   = (const float*)d_in[22];
    const float* bn_v   = (const float*)d_in[23];
    const float* W_lin1 = (const float*)d_in[24];
    const float* b_lin1 = (const float*)d_in[25];
    const float* W_lin2 = (const float*)d_in[26];
    const float* b_lin2 = (const float*)d_in[27];
    float* out = (float*)d_out;

    const int N0 = in_sizes[3];
    const int E0 = in_sizes[2];
    const int N1 = in_sizes[7];
    const int E1 = in_sizes[6];
    const int H = HC;

    const int* row0 = ei0;
    const int* col0 = ei0 + E0;
    const int* nodeC = cover;
    const int* clusC = cover + N0;
    const int* row1 = ei1;
    const int* col1 = ei1 + E1;

    float *xw, *x1, *x2, *h, *dinv0, *coef0, *h1cat, *yw, *y1, *y2, *hb, *dinv1, *coef1, *z;
    cudaGetSymbolAddress((void**)&xw, g_xw);
    cudaGetSymbolAddress((void**)&x1, g_x1);
    cudaGetSymbolAddress((void**)&x2, g_x2);
    cudaGetSymbolAddress((void**)&h,  g_h);
    cudaGetSymbolAddress((void**)&dinv0, g_dinv0);
    cudaGetSymbolAddress((void**)&coef0, g_coef0);
    cudaGetSymbolAddress((void**)&h1cat, g_h1cat);
    cudaGetSymbolAddress((void**)&yw, g_yw);
    cudaGetSymbolAddress((void**)&y1, g_y1);
    cudaGetSymbolAddress((void**)&y2, g_y2);
    cudaGetSymbolAddress((void**)&hb, g_hb);
    cudaGetSymbolAddress((void**)&dinv1, g_dinv1);
    cudaGetSymbolAddress((void**)&coef1, g_coef1);
    cudaGetSymbolAddress((void**)&z,  g_z);

    int *cnt0, *start0, *cur0, *srow0, *cnt1, *start1, *cur1, *srow1;
    float *scoef0, *scoef1;
    cudaGetSymbolAddress((void**)&cnt0, g_cnt0);
    cudaGetSymbolAddress((void**)&start0, g_start0);
    cudaGetSymbolAddress((void**)&cur0, g_cur0);
    cudaGetSymbolAddress((void**)&srow0, g_srow0);
    cudaGetSymbolAddress((void**)&scoef0, g_scoef0);
    cudaGetSymbolAddress((void**)&cnt1, g_cnt1);
    cudaGetSymbolAddress((void**)&start1, g_start1);
    cudaGetSymbolAddress((void**)&cur1, g_cur1);
    cudaGetSymbolAddress((void**)&srow1, g_srow1);
    cudaGetSymbolAddress((void**)&scoef1, g_scoef1);

    cudaFuncSetAttribute(gemm_tc_kernel,
                         cudaFuncAttributeMaxDynamicSharedMemorySize, GEMM_SMEM);

    dim3 gemmBlk(256);
    dim3 g0(H / GBN, ceil_div(N0, GBM));
    dim3 g1(H / GBN, ceil_div(N1, GBM));

    // ncu (-s 5 -c 1 incl. 2 harness launches) profiles MY 4th launch (the big GEMM).
    fill_kernel<<<ceil_div(N0, 256), 256>>>(dinv0, N0, 1.f);                 // 1
    deg_accum_kernel<<<ceil_div(E0, 256), 256>>>(col0, ew0, dinv0, E0);      // 2
    finalize_dinv_kernel<<<ceil_div(N0, 256), 256>>>(dinv0, N0);             // 3

    // ---- level 0: GCN 1 GEMM (fused: xw=x@W, x1=b+dinv^2*xw) ----
    gemm_tc_kernel<<<g0, gemmBlk, GEMM_SMEM>>>(x, x, FC, FC, W_in0, b_in0, xw, x1, dinv0,
                                               N0, H, 0, 0);                 // 4 (profiled)

    // ---- level-0 CSR build ----
    edge_coef_kernel<<<ceil_div(E0, 256), 256>>>(row0, col0, ew0, dinv0, coef0, E0);
    filli_kernel<<<ceil_div(N0, 256), 256>>>(cnt0, N0, 0);
    count_kernel<<<ceil_div(E0, 256), 256>>>(col0, cnt0, E0);
    scan_kernel<<<1, 1024>>>(cnt0, start0, cur0, N0);
    emit_kernel<<<ceil_div(E0, 256), 256>>>(row0, col0, coef0, cur0, srow0, scoef0, E0);

    // ---- level 0: GCN 1 aggregate ----
    gcn_gather_csr<<<ceil_div(N0, 4), 256>>>(xw, srow0, scoef0, start0, x1, N0);

    // level-1 prep (independent)
    fill_kernel<<<ceil_div(N1, 256), 256>>>(dinv1, N1, 1.f);
    deg_accum_kernel<<<ceil_div(E1, 256), 256>>>(col1, ew1, dinv1, E1);
    finalize_dinv_kernel<<<ceil_div(N1, 256), 256>>>(dinv1, N1);
    edge_coef_kernel<<<ceil_div(E1, 256), 256>>>(row1, col1, ew1, dinv1, coef1, E1);
    filli_kernel<<<ceil_div(N1, 256), 256>>>(cnt1, N1, 0);
    count_kernel<<<ceil_div(E1, 256), 256>>>(col1, cnt1, E1);
    scan_kernel<<<1, 1024>>>(cnt1, start1, cur1, N1);
    emit_kernel<<<ceil_div(E1, 256), 256>>>(row1, col1, coef1, cur1, srow1, scoef1, E1);
    fill_kernel<<<ceil_div(BC * 4 * H, 256), 256>>>(z, BC * 4 * H, 0.f);
    fill_kernel<<<ceil_div(N1 * 2 * H, 256), 256>>>(h1cat, N1 * 2 * H, 0.f);

    // ---- level 0: GCN 2 ----
    gemm_tc_kernel<<<g0, gemmBlk, GEMM_SMEM>>>(x1, x1, H, H, W_in1, b_in1, xw, x2, dinv0,
                                               N0, H, 1, 0);
    gcn_gather_csr<<<ceil_div(N0, 4), 256>>>(xw, srow0, scoef0, start0, x2, N0);

    // ---- level 0: JK cat + linear + relu ----
    gemm_tc_kernel<<<g0, gemmBlk, GEMM_SMEM>>>(x1, x2, H, 2 * H, W_jk_in, b_jk_in, h,
                                               NULL, NULL, N0, H, 1, 1);

    // ---- fused level-0 pools (batch -> z, cover -> h1cat) ----
    dualpool_kernel<<<ceil_div(N0, 128), 256>>>(h, batch0, nodeC, clusC, N0,
                                                z + 0, z + H,
                                                h1cat + 0, h1cat + H, 128);

    // ---- level 1: GCN 1 ----
    gemm_tc_kernel<<<g1, gemmBlk, GEMM_SMEM>>>(h1cat, h1cat, 2 * H, 2 * H, W_b0, b_b0,
                                               yw, y1, dinv1, N1, H, 0, 0);
    gcn_gather_csr<<<ceil_div(N1, 4), 256>>>(yw, srow1, scoef1, start1, y1, N1);

    // ---- level 1: GCN 2 ----
    gemm_tc_kernel<<<g1, gemmBlk, GEMM_SMEM>>>(y1, y1, H, H, W_b1, b_b1, yw, y2, dinv1,
                                               N1, H, 1, 0);
    gcn_gather_csr<<<ceil_div(N1, 4), 256>>>(yw, srow1, scoef1, start1, y2, N1);

    // ---- level 1: JK ----
    gemm_tc_kernel<<<g1, gemmBlk, GEMM_SMEM>>>(y1, y2, H, 2 * H, W_jk_b, b_jk_b, hb,
                                               NULL, NULL, N1, H, 1, 1);

    // ---- level-1 batch pool ----
    segpool_kernel<<<ceil_div(N1, 128), 256>>>(hb, batch1, N1, H,
                                               z + 2 * H, z + 3 * H, 4 * H, 128);

    // ---- head ----
    head_kernel<<<BC, 256>>>(z, bn_g, bn_b, bn_m, bn_v,
                             W_lin1, b_lin1, W_lin2, b_lin2, out);
}

// round 16
// speedup vs baseline: 1.2288x; 1.0535x over previous
#include <cuda_runtime.h>
#include <math.h>
#include <stdint.h>

#define N0C 50000
#define E0C 800000
#define N1C 10000
#define E1C 160000
#define FC  128
#define HC  256
#define BC  64

// ---------------- static scratch ----------------
__device__ float g_xw [N0C * HC];
__device__ float g_x1 [N0C * HC];
__device__ float g_x2 [N0C * HC];
__device__ float g_h  [N0C * HC];
__device__ float g_dinv0[N0C];
__device__ float g_coef0[E0C];

__device__ float g_h1cat[N1C * 2 * HC];
__device__ float g_yw [N1C * HC];
__device__ float g_y1 [N1C * HC];
__device__ float g_y2 [N1C * HC];
__device__ float g_hb [N1C * HC];
__device__ float g_dinv1[N1C];
__device__ float g_coef1[E1C];

__device__ float g_z [BC * 4 * HC];

// CSR scratch
__device__ int   g_cnt0[N0C];
__device__ int   g_start0[N0C + 1];
__device__ int   g_cur0[N0C];
__device__ int   g_srow0[E0C];
__device__ float g_scoef0[E0C];
__device__ int   g_cnt1[N1C];
__device__ int   g_start1[N1C + 1];
__device__ int   g_cur1[N1C];
__device__ int   g_srow1[E1C];
__device__ float g_scoef1[E1C];

// ---------------- utility kernels ----------------
__global__ void fill_kernel(float* p, int n, float v) {
    int i = blockIdx.x * blockDim.x + threadIdx.x;
    if (i < n) p[i] = v;
}

__global__ void filli_kernel(int* p, int n, int v) {
    int i = blockIdx.x * blockDim.x + threadIdx.x;
    if (i < n) p[i] = v;
}

__global__ void deg_accum_kernel(const int* __restrict__ col,
                                 const float* __restrict__ ew,
                                 float* __restrict__ deg, int E) {
    int e = blockIdx.x * blockDim.x + threadIdx.x;
    if (e < E) atomicAdd(&deg[col[e]], ew[e]);
}

__global__ void finalize_dinv_kernel(float* deg, int n) {
    int i = blockIdx.x * blockDim.x + threadIdx.x;
    if (i < n) {
        float d = deg[i];
        deg[i] = (d > 0.f) ? rsqrtf(d) : 0.f;
    }
}

__global__ void edge_coef_kernel(const int* __restrict__ row,
                                 const int* __restrict__ col,
                                 const float* __restrict__ ew,
                                 const float* __restrict__ dinv,
                                 float* __restrict__ coef, int E) {
    int e = blockIdx.x * blockDim.x + threadIdx.x;
    if (e < E) coef[e] = dinv[row[e]] * ew[e] * dinv[col[e]];
}

// ---------------- CSR build ----------------
__global__ void count_kernel(const int* __restrict__ col,
                             int* __restrict__ cnt, int E) {
    int e = blockIdx.x * blockDim.x + threadIdx.x;
    if (e < E) atomicAdd(&cnt[col[e]], 1);
}

__global__ void scan_kernel(const int* __restrict__ cnt,
                            int* __restrict__ start,
                            int* __restrict__ cursor, int n) {
    __shared__ int part[1024];
    int tid = threadIdx.x;
    int chunk = (n + 1023) / 1024;
    int base = tid * chunk;
    int s = 0;
    for (int i = 0; i < chunk; i++) {
        int idx = base + i;
        if (idx < n) s += cnt[idx];
    }
    part[tid] = s;
    __syncthreads();
    for (int off = 1; off < 1024; off <<= 1) {
        int v = (tid >= off) ? part[tid - off] : 0;
        __syncthreads();
        part[tid] += v;
        __syncthreads();
    }
    int run = (tid == 0) ? 0 : part[tid - 1];
    for (int i = 0; i < chunk; i++) {
        int idx = base + i;
        if (idx < n) {
            start[idx] = run;
            cursor[idx] = run;
            run += cnt[idx];
        }
    }
    if (tid == 1023) start[n] = run;
}

__global__ void emit_kernel(const int* __restrict__ row,
                            const int* __restrict__ col,
                            const float* __restrict__ coef,
                            int* __restrict__ cursor,
                            int* __restrict__ srow,
                            float* __restrict__ scoef, int E) {
    int e = blockIdx.x * blockDim.x + threadIdx.x;
    if (e < E) {
        int c = col[e];
        int p = atomicAdd(&cursor[c], 1);
        srow[p] = row[e];
        scoef[p] = coef[e];
    }
}

// Gather-by-destination: out[c,:] += sum_e coef*xw[row,:]. No output atomics.
__global__ void gcn_gather_csr(const float* __restrict__ xw,
                               const int* __restrict__ srow,
                               const float* __restrict__ scoef,
                               const int* __restrict__ start,
                               float* __restrict__ out, int N) {
    int f4 = threadIdx.x & 63;
    int slot = threadIdx.x >> 6;
    int c = blockIdx.x * 4 + slot;
    if (c >= N) return;
    int p  = start[c];
    int pe = start[c + 1];
    float4 acc = make_float4(0.f, 0.f, 0.f, 0.f);
    for (; p + 1 < pe; p += 2) {
        int r0 = srow[p],     r1 = srow[p + 1];
        float c0 = scoef[p],  c1 = scoef[p + 1];
        float4 v0 = *reinterpret_cast<const float4*>(xw + (size_t)r0 * HC + f4 * 4);
        float4 v1 = *reinterpret_cast<const float4*>(xw + (size_t)r1 * HC + f4 * 4);
        acc.x += c0 * v0.x + c1 * v1.x;
        acc.y += c0 * v0.y + c1 * v1.y;
        acc.z += c0 * v0.z + c1 * v1.z;
        acc.w += c0 * v0.w + c1 * v1.w;
    }
    if (p < pe) {
        int r = srow[p];
        float cf = scoef[p];
        float4 v = *reinterpret_cast<const float4*>(xw + (size_t)r * HC + f4 * 4);
        acc.x += cf * v.x; acc.y += cf * v.y;
        acc.z += cf * v.z; acc.w += cf * v.w;
    }
    float4* dst = reinterpret_cast<float4*>(out + (size_t)c * HC + f4 * 4);
    float4 cur = *dst;
    cur.x += acc.x; cur.y += acc.y; cur.z += acc.z; cur.w += acc.w;
    *dst = cur;
}

// ---------------- bf16 1-term tensor-core GEMM (A bf16, B bf16) ----------
// 128x128 tile, 2 CTAs/SM. 8KB smem per buffer.
#define GBM 128
#define GBN 128
#define S_AHI 0
#define S_BHI 1024
#define S_BUF 2048

__device__ __forceinline__ uint32_t pack_bf16(float fx, float fy) {
    uint32_t h;
    asm("cvt.rn.bf16x2.f32 %0, %1, %2;" : "=r"(h) : "f"(fy), "f"(fx));
    return h;
}

__device__ __forceinline__ void mma_bf16(float* c, const uint32_t* a, const uint32_t* b) {
    asm volatile(
        "mma.sync.aligned.m16n8k16.row.col.f32.bf16.bf16.f32 "
        "{%0,%1,%2,%3}, {%4,%5,%6,%7}, {%8,%9}, {%0,%1,%2,%3};"
        : "+f"(c[0]), "+f"(c[1]), "+f"(c[2]), "+f"(c[3])
        : "r"(a[0]), "r"(a[1]), "r"(a[2]), "r"(a[3]), "r"(b[0]), "r"(b[1]));
}

__device__ __forceinline__ int a_swz(int lin) {
    return lin ^ (((lin >> 5) & 3) << 2);
}

__global__ __launch_bounds__(256, 2)
void gemm_tc_kernel(const float* __restrict__ A1,
                    const float* __restrict__ A2,
                    int K1, int K,
                    const float* __restrict__ W,
                    const float* __restrict__ bias,
                    float* __restrict__ C,
                    float* __restrict__ C2,
                    const float* __restrict__ dinv,
                    int M, int N,
                    int reluIn, int reluOut) {
    extern __shared__ uint32_t smem[];

    const int tid  = threadIdx.x;
    const int lane = tid & 31;
    const int warp = tid >> 5;
    const int warp_m = warp & 1;
    const int warp_n = warp >> 1;
    const int bm = blockIdx.y * GBM;
    const int bn = blockIdx.x * GBN;
    const int K2 = K - K1;

    const int am     = tid >> 1;
    const int ak0    = (tid & 1) * 8;
    const int amtile = am >> 4;
    const int ar     = am & 15;
    const int abase  = amtile * 128 + (ar & 7) * 16 + (ar >> 3);

    const int bkp  = tid >> 5;
    const int bn0  = (tid & 31) * 4;
    const int bkt  = (bkp & 3) * 2 + (bkp >> 2);

    float c[4][4][4];
#pragma unroll
    for (int mi = 0; mi < 4; mi++)
#pragma unroll
        for (int ni = 0; ni < 4; ni++)
#pragma unroll
            for (int q = 0; q < 4; q++) c[mi][ni][q] = 0.f;

    const int nt = K / 16;

    float4 va[2], vw[2];
    auto LOAD_TILE = [&](int t) {
        const int gk0 = t * 16;
#pragma unroll
        for (int i = 0; i < 2; i++) {
            int gk = gk0 + ak0 + i * 4;
            int gm = bm + am;
            float4 v = make_float4(0.f, 0.f, 0.f, 0.f);
            if (gm < M) {
                const float* src = (gk < K1) ? (A1 + (size_t)gm * K1 + gk)
                                             : (A2 + (size_t)gm * K2 + (gk - K1));
                v = *reinterpret_cast<const float4*>(src);
            }
            if (reluIn) {
                v.x = fmaxf(v.x, 0.f); v.y = fmaxf(v.y, 0.f);
                v.z = fmaxf(v.z, 0.f); v.w = fmaxf(v.w, 0.f);
            }
            va[i] = v;
        }
        int r0 = gk0 + 2 * bkp;
        vw[0] = *reinterpret_cast<const float4*>(W + (size_t)r0 * N + bn + bn0);
        vw[1] = *reinterpret_cast<const float4*>(W + (size_t)(r0 + 1) * N + bn + bn0);
    };

    auto STORE_TILE = [&](int buf) {
        uint32_t* sb = smem + buf * S_BUF;
#pragma unroll
        for (int i = 0; i < 2; i++) {
            int p = (ak0 >> 1) + 2 * i;
            uint32_t h = pack_bf16(va[i].x, va[i].y);
            int lin = abase + (p & 3) * 4 + (p >> 2) * 2;
            sb[S_AHI + a_swz(lin)] = h;
            h = pack_bf16(va[i].z, va[i].w);
            p++;
            lin = abase + (p & 3) * 4 + (p >> 2) * 2;
            sb[S_AHI + a_swz(lin)] = h;
        }
        float f0[4] = {vw[0].x, vw[0].y, vw[0].z, vw[0].w};
        float f1[4] = {vw[1].x, vw[1].y, vw[1].z, vw[1].w};
#pragma unroll
        for (int q = 0; q < 4; q++) {
            int n = bn0 + q;
            int ntile = n >> 3;
            uint32_t h = pack_bf16(f0[q], f1[q]);
            int lin = ntile * 64 + (n & 7) * 8 + bkt;
            int sw = lin ^ ((ntile & 15) << 1);
            sb[S_BHI + sw] = h;
        }
    };

    LOAD_TILE(0);
    STORE_TILE(0);
    __syncthreads();

    int cur = 0;
    for (int t = 0; t < nt; t++) {
        const bool more = (t + 1 < nt);
        if (more) LOAD_TILE(t + 1);

        const uint32_t* sb = smem + cur * S_BUF;

        uint32_t bh[4][2];
#pragma unroll
        for (int ni = 0; ni < 4; ni++) {
            int ntile = warp_n * 4 + ni;
            int lin = ntile * 64 + lane * 2;
            int sw = lin ^ ((ntile & 15) << 1);
            uint2 h = *reinterpret_cast<const uint2*>(sb + S_BHI + sw);
            bh[ni][0] = h.x; bh[ni][1] = h.y;
        }

#pragma unroll
        for (int mi = 0; mi < 4; mi++) {
            int mtile = warp_m * 4 + mi;
            int lin = mtile * 128 + lane * 4;
            int sw = a_swz(lin);
            uint4 h4 = *reinterpret_cast<const uint4*>(sb + S_AHI + sw);
            uint32_t ah[4] = {h4.x, h4.y, h4.z, h4.w};
#pragma unroll
            for (int ni = 0; ni < 4; ni++)
                mma_bf16(c[mi][ni], ah, bh[ni]);
        }

        if (more) {
            STORE_TILE(cur ^ 1);
            __syncthreads();
            cur ^= 1;
        }
    }

    // ---- epilogue ----
    const int gid = lane >> 2;
    const int tig = lane & 3;
#pragma unroll
    for (int mi = 0; mi < 4; mi++) {
#pragma unroll
        for (int half = 0; half < 2; half++) {
            int gm = bm + warp_m * 64 + mi * 16 + gid + half * 8;
            if (gm >= M) continue;
            float dd = 0.f;
            if (C2) { float dv = dinv[gm]; dd = dv * dv; }
#pragma unroll
            for (int ni = 0; ni < 4; ni++) {
                int gn = bn + warp_n * 32 + ni * 8 + tig * 2;
                float v0 = c[mi][ni][half * 2 + 0];
                float v1 = c[mi][ni][half * 2 + 1];
                if (C2) {
                    *reinterpret_cast<float2*>(C + (size_t)gm * N + gn) =
                        make_float2(v0, v1);
                    float b0 = bias[gn], b1 = bias[gn + 1];
                    *reinterpret_cast<float2*>(C2 + (size_t)gm * N + gn) =
                        make_float2(b0 + dd * v0, b1 + dd * v1);
                } else {
                    if (bias) { v0 += bias[gn]; v1 += bias[gn + 1]; }
                    if (reluOut) { v0 = fmaxf(v0, 0.f); v1 = fmaxf(v1, 0.f); }
                    *reinterpret_cast<float2*>(C + (size_t)gm * N + gn) =
                        make_float2(v0, v1);
                }
            }
        }
    }
}

// ---------------- segment pool (sum + max), values >= 0 -----------
__global__ void segpool_kernel(const float* __restrict__ in,
                               const int* __restrict__ seg,
                               int M, int F,
                               float* __restrict__ outSum,
                               float* __restrict__ outMax,
                               int ldOut, int nodesPerBlock) {
    int f = threadIdx.x;
    int n0 = blockIdx.x * nodesPerBlock;
    int n1 = n0 + nodesPerBlock;
    if (n1 > M) n1 = M;
    if (n0 >= n1) return;
    int cur = seg[n0];
    float s = 0.f, mx = 0.f;
    for (int n = n0; n < n1; n++) {
        int sg = seg[n];
        if (sg != cur) {
            atomicAdd(&outSum[cur * ldOut + f], s);
            atomicMax((int*)&outMax[cur * ldOut + f], __float_as_int(mx));
            s = 0.f; mx = 0.f; cur = sg;
        }
        float v = in[(size_t)n * F + f];
        s += v;
        mx = fmaxf(mx, v);
    }
    atomicAdd(&outSum[cur * ldOut + f], s);
    atomicMax((int*)&outMax[cur * ldOut + f], __float_as_int(mx));
}

// Fused dual pool over level-0 nodes: batch pool into z, cover pool into h1cat.
__global__ void dualpool_kernel(const float* __restrict__ h,
                                const int* __restrict__ batch,
                                const int* __restrict__ nodeIdx,
                                const int* __restrict__ clus,
                                int M,
                                float* __restrict__ zSum, float* __restrict__ zMax,
                                float* __restrict__ cSum, float* __restrict__ cMax,
                                int nodesPerBlock) {
    int f = threadIdx.x;
    int n0 = blockIdx.x * nodesPerBlock;
    int n1 = n0 + nodesPerBlock;
    if (n1 > M) n1 = M;
    if (n0 >= n1) return;
    int curB = batch[n0], curC = clus[n0];
    float sB = 0.f, mB = 0.f, sC = 0.f, mC = 0.f;
    for (int n = n0; n < n1; n++) {
        int b = batch[n];
        int cl = clus[n];
        if (b != curB) {
            atomicAdd(&zSum[curB * (4 * HC) + f], sB);
            atomicMax((int*)&zMax[curB * (4 * HC) + f], __float_as_int(mB));
            sB = 0.f; mB = 0.f; curB = b;
        }
        if (cl != curC) {
            atomicAdd(&cSum[curC * (2 * HC) + f], sC);
            atomicMax((int*)&cMax[curC * (2 * HC) + f], __float_as_int(mC));
            sC = 0.f; mC = 0.f; curC = cl;
        }
        float v = h[(size_t)n * HC + f];
        sB += v; mB = fmaxf(mB, v);
        int ni = nodeIdx[n];
        float vc = (ni == n) ? v : h[(size_t)ni * HC + f];
        sC += vc; mC = fmaxf(mC, vc);
    }
    atomicAdd(&zSum[curB * (4 * HC) + f], sB);
    atomicMax((int*)&zMax[curB * (4 * HC) + f], __float_as_int(mB));
    atomicAdd(&cSum[curC * (2 * HC) + f], sC);
    atomicMax((int*)&cMax[curC * (2 * HC) + f], __float_as_int(mC));
}

// ---------------- head ----------------
__global__ void head_kernel(const float* __restrict__ z,
                            const float* __restrict__ gamma,
                            const float* __restrict__ beta,
                            const float* __restrict__ mean,
                            const float* __restrict__ var,
                            const float* __restrict__ W1,
                            const float* __restrict__ b1,
                            const float* __restrict__ W2,
                            const float* __restrict__ b2,
                            float* __restrict__ out) {
    __shared__ float zn[4 * HC];
    __shared__ float s1[HC];
    __shared__ float logits[16];
    int b = blockIdx.x;
    int t = threadIdx.x;
    for (int k = t; k < 4 * HC; k += 256) {
        float v = z[b * 4 * HC + k];
        zn[k] = (v - mean[k]) * rsqrtf(var[k] + 1e-5f) * gamma[k] + beta[k];
    }
    __syncthreads();
    float acc = b1[t];
    for (int k = 0; k < 4 * HC; k++) acc += zn[k] * W1[k * HC + t];
    s1[t] = fmaxf(acc, 0.f);
    __syncthreads();
    if (t < 10) {
        float a2 = b2[t];
        for (int k = 0; k < HC; k++) a2 += s1[k] * W2[k * 10 + t];
        logits[t] = a2;
    }
    __syncthreads();
    if (t == 0) {
        float mx = logits[0];
        for (int c = 1; c < 10; c++) mx = fmaxf(mx, logits[c]);
        float e[10], sum = 0.f;
        for (int c = 0; c < 10; c++) { e[c] = expf(logits[c] - mx); sum += e[c]; }
        float inv = 1.f / sum;
        for (int c = 0; c < 10; c++) out[b * 10 + c] = e[c] * inv;
    }
}

// ---------------- orchestration ----------------
static inline int ceil_div(int a, int b) { return (a + b - 1) / b; }
#define GEMM_SMEM (2 * S_BUF * (int)sizeof(uint32_t))

extern "C" void kernel_launch(void* const* d_in, const int* in_sizes, int n_in,
                              void* d_out, int out_size) {
    const float* x      = (const float*)d_in[0];
    const int*   ei0    = (const int*)d_in[1];
    const float* ew0    = (const float*)d_in[2];
    const int*   batch0 = (const int*)d_in[3];
    const int*   cover  = (const int*)d_in[4];
    const int*   ei1    = (const int*)d_in[5];
    const float* ew1    = (const float*)d_in[6];
    const int*   batch1 = (const int*)d_in[7];
    const float* W_in0  = (const float*)d_in[8];
    const float* b_in0  = (const float*)d_in[9];
    const float* W_in1  = (const float*)d_in[10];
    const float* b_in1  = (const float*)d_in[11];
    const float* W_jk_in= (const float*)d_in[12];
    const float* b_jk_in= (const float*)d_in[13];
    const float* W_b0   = (const float*)d_in[14];
    const float* b_b0   = (const float*)d_in[15];
    const float* W_b1   = (const float*)d_in[16];
    const float* b_b1   = (const float*)d_in[17];
    const float* W_jk_b = (const float*)d_in[18];
    const float* b_jk_b = (const float*)d_in[19];
    const float* bn_g   = (const float*)d_in[20];
    const float* bn_b   = (const float*)d_in[21];
    const float* bn_m   = (const float*)d_in[22];
    const float* bn_v   = (const float*)d_in[23];
    const float* W_lin1 = (const float*)d_in[24];
    const float* b_lin1 = (const float*)d_in[25];
    const float* W_lin2 = (const float*)d_in[26];
    const float* b_lin2 = (const float*)d_in[27];
    float* out = (float*)d_out;

    const int N0 = in_sizes[3];
    const int E0 = in_sizes[2];
    const int N1 = in_sizes[7];
    const int E1 = in_sizes[6];
    const int H = HC;

    const int* row0 = ei0;
    const int* col0 = ei0 + E0;
    const int* nodeC = cover;
    const int* clusC = cover + N0;
    const int* row1 = ei1;
    const int* col1 = ei1 + E1;

    float *xw, *x1, *x2, *h, *dinv0, *coef0, *h1cat, *yw, *y1, *y2, *hb, *dinv1, *coef1, *z;
    cudaGetSymbolAddress((void**)&xw, g_xw);
    cudaGetSymbolAddress((void**)&x1, g_x1);
    cudaGetSymbolAddress((void**)&x2, g_x2);
    cudaGetSymbolAddress((void**)&h,  g_h);
    cudaGetSymbolAddress((void**)&dinv0, g_dinv0);
    cudaGetSymbolAddress((void**)&coef0, g_coef0);
    cudaGetSymbolAddress((void**)&h1cat, g_h1cat);
    cudaGetSymbolAddress((void**)&yw, g_yw);
    cudaGetSymbolAddress((void**)&y1, g_y1);
    cudaGetSymbolAddress((void**)&y2, g_y2);
    cudaGetSymbolAddress((void**)&hb, g_hb);
    cudaGetSymbolAddress((void**)&dinv1, g_dinv1);
    cudaGetSymbolAddress((void**)&coef1, g_coef1);
    cudaGetSymbolAddress((void**)&z,  g_z);

    int *cnt0, *start0, *cur0, *srow0, *cnt1, *start1, *cur1, *srow1;
    float *scoef0, *scoef1;
    cudaGetSymbolAddress((void**)&cnt0, g_cnt0);
    cudaGetSymbolAddress((void**)&start0, g_start0);
    cudaGetSymbolAddress((void**)&cur0, g_cur0);
    cudaGetSymbolAddress((void**)&srow0, g_srow0);
    cudaGetSymbolAddress((void**)&scoef0, g_scoef0);
    cudaGetSymbolAddress((void**)&cnt1, g_cnt1);
    cudaGetSymbolAddress((void**)&start1, g_start1);
    cudaGetSymbolAddress((void**)&cur1, g_cur1);
    cudaGetSymbolAddress((void**)&srow1, g_srow1);
    cudaGetSymbolAddress((void**)&scoef1, g_scoef1);

    cudaFuncSetAttribute(gemm_tc_kernel,
                         cudaFuncAttributeMaxDynamicSharedMemorySize, GEMM_SMEM);

    dim3 gemmBlk(256);
    dim3 g0(H / GBN, ceil_div(N0, GBM));
    dim3 g1(H / GBN, ceil_div(N1, GBM));

    // ncu (-s 5 -c 1 incl. 2 harness launches) profiles MY 4th launch (the big GEMM).
    fill_kernel<<<ceil_div(N0, 256), 256>>>(dinv0, N0, 1.f);                 // 1
    deg_accum_kernel<<<ceil_div(E0, 256), 256>>>(col0, ew0, dinv0, E0);      // 2
    finalize_dinv_kernel<<<ceil_div(N0, 256), 256>>>(dinv0, N0);             // 3

    // ---- level 0: GCN 1 GEMM (fused: xw=x@W, x1=b+dinv^2*xw) ----
    gemm_tc_kernel<<<g0, gemmBlk, GEMM_SMEM>>>(x, x, FC, FC, W_in0, b_in0, xw, x1, dinv0,
                                               N0, H, 0, 0);                 // 4 (profiled)

    // ---- level-0 CSR build ----
    edge_coef_kernel<<<ceil_div(E0, 256), 256>>>(row0, col0, ew0, dinv0, coef0, E0);
    filli_kernel<<<ceil_div(N0, 256), 256>>>(cnt0, N0, 0);
    count_kernel<<<ceil_div(E0, 256), 256>>>(col0, cnt0, E0);
    scan_kernel<<<1, 1024>>>(cnt0, start0, cur0, N0);
    emit_kernel<<<ceil_div(E0, 256), 256>>>(row0, col0, coef0, cur0, srow0, scoef0, E0);

    // ---- level 0: GCN 1 aggregate ----
    gcn_gather_csr<<<ceil_div(N0, 4), 256>>>(xw, srow0, scoef0, start0, x1, N0);

    // level-1 prep (independent)
    fill_kernel<<<ceil_div(N1, 256), 256>>>(dinv1, N1, 1.f);
    deg_accum_kernel<<<ceil_div(E1, 256), 256>>>(col1, ew1, dinv1, E1);
    finalize_dinv_kernel<<<ceil_div(N1, 256), 256>>>(dinv1, N1);
    edge_coef_kernel<<<ceil_div(E1, 256), 256>>>(row1, col1, ew1, dinv1, coef1, E1);
    filli_kernel<<<ceil_div(N1, 256), 256>>>(cnt1, N1, 0);
    count_kernel<<<ceil_div(E1, 256), 256>>>(col1, cnt1, E1);
    scan_kernel<<<1, 1024>>>(cnt1, start1, cur1, N1);
    emit_kernel<<<ceil_div(E1, 256), 256>>>(row1, col1, coef1, cur1, srow1, scoef1, E1);
    fill_kernel<<<ceil_div(BC * 4 * H, 256), 256>>>(z, BC * 4 * H, 0.f);
    fill_kernel<<<ceil_div(N1 * 2 * H, 256), 256>>>(h1cat, N1 * 2 * H, 0.f);

    // ---- level 0: GCN 2 ----
    gemm_tc_kernel<<<g0, gemmBlk, GEMM_SMEM>>>(x1, x1, H, H, W_in1, b_in1, xw, x2, dinv0,
                                               N0, H, 1, 0);
    gcn_gather_csr<<<ceil_div(N0, 4), 256>>>(xw, srow0, scoef0, start0, x2, N0);

    // ---- level 0: JK cat + linear + relu ----
    gemm_tc_kernel<<<g0, gemmBlk, GEMM_SMEM>>>(x1, x2, H, 2 * H, W_jk_in, b_jk_in, h,
                                               NULL, NULL, N0, H, 1, 1);

    // ---- fused level-0 pools (batch -> z, cover -> h1cat) ----
    dualpool_kernel<<<ceil_div(N0, 128), 256>>>(h, batch0, nodeC, clusC, N0,
                                                z + 0, z + H,
                                                h1cat + 0, h1cat + H, 128);

    // ---- level 1: GCN 1 ----
    gemm_tc_kernel<<<g1, gemmBlk, GEMM_SMEM>>>(h1cat, h1cat, 2 * H, 2 * H, W_b0, b_b0,
                                               yw, y1, dinv1, N1, H, 0, 0);
    gcn_gather_csr<<<ceil_div(N1, 4), 256>>>(yw, srow1, scoef1, start1, y1, N1);

    // ---- level 1: GCN 2 ----
    gemm_tc_kernel<<<g1, gemmBlk, GEMM_SMEM>>>(y1, y1, H, H, W_b1, b_b1, yw, y2, dinv1,
                                               N1, H, 1, 0);
    gcn_gather_csr<<<ceil_div(N1, 4), 256>>>(yw, srow1, scoef1, start1, y2, N1);

    // ---- level 1: JK ----
    gemm_tc_kernel<<<g1, gemmBlk, GEMM_SMEM>>>(y1, y2, H, 2 * H, W_jk_b, b_jk_b, hb,
                                               NULL, NULL, N1, H, 1, 1);

    // ---- level-1 batch pool ----
    segpool_kernel<<<ceil_div(N1, 128), 256>>>(hb, batch1, N1, H,
                                               z + 2 * H, z + 3 * H, 4 * H, 128);

    // ---- head ----
    head_kernel<<<BC, 256>>>(z, bn_g, bn_b, bn_m, bn_v,
                             W_lin1, b_lin1, W_lin2, b_lin2, out);
}

// round 17
// speedup vs baseline: 1.3576x; 1.1048x over previous
#include <cuda_runtime.h>
#include <cuda_bf16.h>
#include <math.h>
#include <stdint.h>

#define N0C 50000
#define E0C 800000
#define N1C 10000
#define E1C 160000
#define FC  128
#define HC  256
#define HW  (HC / 2)   // packed words per row
#define BC  64

// ---------------- static scratch ----------------
// packed bf16x2 activations (word j = features 2j, 2j+1)
__device__ uint32_t g_xw [N0C * HW];
__device__ uint32_t g_x1 [N0C * HW];
__device__ uint32_t g_x2 [N0C * HW];
__device__ float    g_h  [N0C * HC];
__device__ float    g_dinv0[N0C];
__device__ float    g_coef0[E0C];

__device__ float    g_h1cat[N1C * 2 * HC];
__device__ uint32_t g_yw [N1C * HW];
__device__ uint32_t g_y1 [N1C * HW];
__device__ uint32_t g_y2 [N1C * HW];
__device__ float    g_hb [N1C * HC];
__device__ float    g_dinv1[N1C];
__device__ float    g_coef1[E1C];

__device__ float g_z [BC * 4 * HC];

// CSR scratch
__device__ int   g_cnt0[N0C];
__device__ int   g_start0[N0C + 1];
__device__ int   g_cur0[N0C];
__device__ int   g_srow0[E0C];
__device__ float g_scoef0[E0C];
__device__ int   g_cnt1[N1C];
__device__ int   g_start1[N1C + 1];
__device__ int   g_cur1[N1C];
__device__ int   g_srow1[E1C];
__device__ float g_scoef1[E1C];

// ---------------- bf16 helpers ----------------
__device__ __forceinline__ uint32_t pack_bf16(float fx, float fy) {
    uint32_t h;
    asm("cvt.rn.bf16x2.f32 %0, %1, %2;" : "=r"(h) : "f"(fy), "f"(fx));
    return h;
}
__device__ __forceinline__ float bflo(uint32_t w) { return __uint_as_float(w << 16); }
__device__ __forceinline__ float bfhi(uint32_t w) { return __uint_as_float(w & 0xFFFF0000u); }
__device__ __forceinline__ uint32_t relu2(uint32_t w) {
    __nv_bfloat162 z = __float2bfloat162_rn(0.f);
    __nv_bfloat162 v = *reinterpret_cast<__nv_bfloat162*>(&w);
    v = __hmax2(v, z);
    return *reinterpret_cast<uint32_t*>(&v);
}

// ---------------- utility kernels ----------------
__global__ void fill_kernel(float* p, int n, float v) {
    int i = blockIdx.x * blockDim.x + threadIdx.x;
    if (i < n) p[i] = v;
}

__global__ void filli_kernel(int* p, int n, int v) {
    int i = blockIdx.x * blockDim.x + threadIdx.x;
    if (i < n) p[i] = v;
}

__global__ void deg_accum_kernel(const int* __restrict__ col,
                                 const float* __restrict__ ew,
                                 float* __restrict__ deg, int E) {
    int e = blockIdx.x * blockDim.x + threadIdx.x;
    if (e < E) atomicAdd(&deg[col[e]], ew[e]);
}

__global__ void finalize_dinv_kernel(float* deg, int n) {
    int i = blockIdx.x * blockDim.x + threadIdx.x;
    if (i < n) {
        float d = deg[i];
        deg[i] = (d > 0.f) ? rsqrtf(d) : 0.f;
    }
}

__global__ void edge_coef_kernel(const int* __restrict__ row,
                                 const int* __restrict__ col,
                                 const float* __restrict__ ew,
                                 const float* __restrict__ dinv,
                                 float* __restrict__ coef, int E) {
    int e = blockIdx.x * blockDim.x + threadIdx.x;
    if (e < E) coef[e] = dinv[row[e]] * ew[e] * dinv[col[e]];
}

// ---------------- CSR build ----------------
__global__ void count_kernel(const int* __restrict__ col,
                             int* __restrict__ cnt, int E) {
    int e = blockIdx.x * blockDim.x + threadIdx.x;
    if (e < E) atomicAdd(&cnt[col[e]], 1);
}

__global__ void scan_kernel(const int* __restrict__ cnt,
                            int* __restrict__ start,
                            int* __restrict__ cursor, int n) {
    __shared__ int part[1024];
    int tid = threadIdx.x;
    int chunk = (n + 1023) / 1024;
    int base = tid * chunk;
    int s = 0;
    for (int i = 0; i < chunk; i++) {
        int idx = base + i;
        if (idx < n) s += cnt[idx];
    }
    part[tid] = s;
    __syncthreads();
    for (int off = 1; off < 1024; off <<= 1) {
        int v = (tid >= off) ? part[tid - off] : 0;
        __syncthreads();
        part[tid] += v;
        __syncthreads();
    }
    int run = (tid == 0) ? 0 : part[tid - 1];
    for (int i = 0; i < chunk; i++) {
        int idx = base + i;
        if (idx < n) {
            start[idx] = run;
            cursor[idx] = run;
            run += cnt[idx];
        }
    }
    if (tid == 1023) start[n] = run;
}

__global__ void emit_kernel(const int* __restrict__ row,
                            const int* __restrict__ col,
                            const float* __restrict__ coef,
                            int* __restrict__ cursor,
                            int* __restrict__ srow,
                            float* __restrict__ scoef, int E) {
    int e = blockIdx.x * blockDim.x + threadIdx.x;
    if (e < E) {
        int c = col[e];
        int p = atomicAdd(&cursor[c], 1);
        srow[p] = row[e];
        scoef[p] = coef[e];
    }
}

// Gather-by-destination on packed bf16 rows: out[c,:] += sum coef*xw[row,:]
__global__ void gcn_gather_csr(const uint32_t* __restrict__ xw,
                               const int* __restrict__ srow,
                               const float* __restrict__ scoef,
                               const int* __restrict__ start,
                               uint32_t* __restrict__ out, int N) {
    int f4 = threadIdx.x & 63;     // covers features f4*4..f4*4+3 = words f4*2, f4*2+1
    int slot = threadIdx.x >> 6;
    int c = blockIdx.x * 4 + slot;
    if (c >= N) return;
    int p  = start[c];
    int pe = start[c + 1];
    float a0 = 0.f, a1 = 0.f, a2 = 0.f, a3 = 0.f;
    for (; p < pe; p++) {
        int r = srow[p];
        float cf = scoef[p];
        uint2 w = *reinterpret_cast<const uint2*>(xw + (size_t)r * HW + f4 * 2);
        a0 += cf * bflo(w.x);
        a1 += cf * bfhi(w.x);
        a2 += cf * bflo(w.y);
        a3 += cf * bfhi(w.y);
    }
    uint2* dst = reinterpret_cast<uint2*>(out + (size_t)c * HW + f4 * 2);
    uint2 cw = *dst;
    uint2 nw;
    nw.x = pack_bf16(bflo(cw.x) + a0, bfhi(cw.x) + a1);
    nw.y = pack_bf16(bflo(cw.y) + a2, bfhi(cw.y) + a3);
    *dst = nw;
}

// ---------------- bf16 tensor-core GEMM (packed or fp32 A) ----------------
#define GBM 128
#define GBN 128
#define S_AHI 0
#define S_BHI 1024
#define S_BUF 2048

__device__ __forceinline__ void mma_bf16(float* c, const uint32_t* a, const uint32_t* b) {
    asm volatile(
        "mma.sync.aligned.m16n8k16.row.col.f32.bf16.bf16.f32 "
        "{%0,%1,%2,%3}, {%4,%5,%6,%7}, {%8,%9}, {%0,%1,%2,%3};"
        : "+f"(c[0]), "+f"(c[1]), "+f"(c[2]), "+f"(c[3])
        : "r"(a[0]), "r"(a[1]), "r"(a[2]), "r"(a[3]), "r"(b[0]), "r"(b[1]));
}

__device__ __forceinline__ int a_swz(int lin) {
    return lin ^ (((lin >> 5) & 3) << 2);
}

// A operands: aPacked ? uint32 word arrays [M, K/2] : fp32 [M, K].
// C/C2: if C2 != NULL, both are packed uint32 [M, N/2] (C raw, C2 self-init);
// else C is fp32 [M, N] with bias+relu.
__global__ __launch_bounds__(256, 2)
void gemm_tc_kernel(const void* __restrict__ A1v,
                    const void* __restrict__ A2v,
                    int K1, int K, int aPacked,
                    const float* __restrict__ W,
                    const float* __restrict__ bias,
                    void* __restrict__ Cv,
                    uint32_t* __restrict__ C2,
                    const float* __restrict__ dinv,
                    int M, int N,
                    int reluIn, int reluOut) {
    extern __shared__ uint32_t smem[];

    const int tid  = threadIdx.x;
    const int lane = tid & 31;
    const int warp = tid >> 5;
    const int warp_m = warp & 1;
    const int warp_n = warp >> 1;
    const int bm = blockIdx.y * GBM;
    const int bn = blockIdx.x * GBN;
    const int K2 = K - K1;

    const int am     = tid >> 1;
    const int ak0    = (tid & 1) * 8;
    const int amtile = am >> 4;
    const int ar     = am & 15;
    const int abase  = amtile * 128 + (ar & 7) * 16 + (ar >> 3);

    const int bkp  = tid >> 5;
    const int bn0  = (tid & 31) * 4;
    const int bkt  = (bkp & 3) * 2 + (bkp >> 2);

    float c[4][4][4];
#pragma unroll
    for (int mi = 0; mi < 4; mi++)
#pragma unroll
        for (int ni = 0; ni < 4; ni++)
#pragma unroll
            for (int q = 0; q < 4; q++) c[mi][ni][q] = 0.f;

    const int nt = K / 16;

    uint32_t aw[4];
    float4 vw[2];
    auto LOAD_TILE = [&](int t) {
        const int gk0 = t * 16;
        int gm = bm + am;
        int gk = gk0 + ak0;
        if (aPacked) {
            uint4 w = make_uint4(0, 0, 0, 0);
            if (gm < M) {
                const uint32_t* src = (gk < K1)
                    ? ((const uint32_t*)A1v + (size_t)gm * (K1 >> 1) + (gk >> 1))
                    : ((const uint32_t*)A2v + (size_t)gm * (K2 >> 1) + ((gk - K1) >> 1));
                w = *reinterpret_cast<const uint4*>(src);
            }
            if (reluIn) {
                w.x = relu2(w.x); w.y = relu2(w.y);
                w.z = relu2(w.z); w.w = relu2(w.w);
            }
            aw[0] = w.x; aw[1] = w.y; aw[2] = w.z; aw[3] = w.w;
        } else {
#pragma unroll
            for (int i = 0; i < 2; i++) {
                int g = gk + i * 4;
                float4 v = make_float4(0.f, 0.f, 0.f, 0.f);
                if (gm < M) {
                    const float* src = (g < K1)
                        ? ((const float*)A1v + (size_t)gm * K1 + g)
                        : ((const float*)A2v + (size_t)gm * K2 + (g - K1));
                    v = *reinterpret_cast<const float4*>(src);
                }
                if (reluIn) {
                    v.x = fmaxf(v.x, 0.f); v.y = fmaxf(v.y, 0.f);
                    v.z = fmaxf(v.z, 0.f); v.w = fmaxf(v.w, 0.f);
                }
                aw[i * 2 + 0] = pack_bf16(v.x, v.y);
                aw[i * 2 + 1] = pack_bf16(v.z, v.w);
            }
        }
        int r0 = gk0 + 2 * bkp;
        vw[0] = *reinterpret_cast<const float4*>(W + (size_t)r0 * N + bn + bn0);
        vw[1] = *reinterpret_cast<const float4*>(W + (size_t)(r0 + 1) * N + bn + bn0);
    };

    auto STORE_TILE = [&](int buf) {
        uint32_t* sb = smem + buf * S_BUF;
#pragma unroll
        for (int j = 0; j < 4; j++) {
            int p = (ak0 >> 1) + j;
            int lin = abase + (p & 3) * 4 + (p >> 2) * 2;
            sb[S_AHI + a_swz(lin)] = aw[j];
        }
        float f0[4] = {vw[0].x, vw[0].y, vw[0].z, vw[0].w};
        float f1[4] = {vw[1].x, vw[1].y, vw[1].z, vw[1].w};
#pragma unroll
        for (int q = 0; q < 4; q++) {
            int n = bn0 + q;
            int ntile = n >> 3;
            uint32_t h = pack_bf16(f0[q], f1[q]);
            int lin = ntile * 64 + (n & 7) * 8 + bkt;
            int sw = lin ^ ((ntile & 15) << 1);
            sb[S_BHI + sw] = h;
        }
    };

    LOAD_TILE(0);
    STORE_TILE(0);
    __syncthreads();

    int cur = 0;
    for (int t = 0; t < nt; t++) {
        const bool more = (t + 1 < nt);
        if (more) LOAD_TILE(t + 1);

        const uint32_t* sb = smem + cur * S_BUF;

        uint32_t bh[4][2];
#pragma unroll
        for (int ni = 0; ni < 4; ni++) {
            int ntile = warp_n * 4 + ni;
            int lin = ntile * 64 + lane * 2;
            int sw = lin ^ ((ntile & 15) << 1);
            uint2 h = *reinterpret_cast<const uint2*>(sb + S_BHI + sw);
            bh[ni][0] = h.x; bh[ni][1] = h.y;
        }

#pragma unroll
        for (int mi = 0; mi < 4; mi++) {
            int mtile = warp_m * 4 + mi;
            int lin = mtile * 128 + lane * 4;
            int sw = a_swz(lin);
            uint4 h4 = *reinterpret_cast<const uint4*>(sb + S_AHI + sw);
            uint32_t ah[4] = {h4.x, h4.y, h4.z, h4.w};
#pragma unroll
            for (int ni = 0; ni < 4; ni++)
                mma_bf16(c[mi][ni], ah, bh[ni]);
        }

        if (more) {
            STORE_TILE(cur ^ 1);
            __syncthreads();
            cur ^= 1;
        }
    }

    // ---- epilogue ----
    const int gid = lane >> 2;
    const int tig = lane & 3;
    const int NW = N >> 1;
#pragma unroll
    for (int mi = 0; mi < 4; mi++) {
#pragma unroll
        for (int half = 0; half < 2; half++) {
            int gm = bm + warp_m * 64 + mi * 16 + gid + half * 8;
            if (gm >= M) continue;
            float dd = 0.f;
            if (C2) { float dv = dinv[gm]; dd = dv * dv; }
#pragma unroll
            for (int ni = 0; ni < 4; ni++) {
                int gn = bn + warp_n * 32 + ni * 8 + tig * 2;
                float v0 = c[mi][ni][half * 2 + 0];
                float v1 = c[mi][ni][half * 2 + 1];
                if (C2) {
                    uint32_t* Cp = (uint32_t*)Cv;
                    size_t word = (size_t)gm * NW + (gn >> 1);
                    Cp[word] = pack_bf16(v0, v1);
                    float b0 = bias[gn], b1 = bias[gn + 1];
                    C2[word] = pack_bf16(b0 + dd * v0, b1 + dd * v1);
                } else {
                    float* Cf = (float*)Cv;
                    if (bias) { v0 += bias[gn]; v1 += bias[gn + 1]; }
                    if (reluOut) { v0 = fmaxf(v0, 0.f); v1 = fmaxf(v1, 0.f); }
                    *reinterpret_cast<float2*>(Cf + (size_t)gm * N + gn) =
                        make_float2(v0, v1);
                }
            }
        }
    }
}

// ---------------- segment pool (sum + max), values >= 0 -----------
__global__ void segpool_kernel(const float* __restrict__ in,
                               const int* __restrict__ seg,
                               int M, int F,
                               float* __restrict__ outSum,
                               float* __restrict__ outMax,
                               int ldOut, int nodesPerBlock) {
    int f = threadIdx.x;
    int n0 = blockIdx.x * nodesPerBlock;
    int n1 = n0 + nodesPerBlock;
    if (n1 > M) n1 = M;
    if (n0 >= n1) return;
    int cur = seg[n0];
    float s = 0.f, mx = 0.f;
    for (int n = n0; n < n1; n++) {
        int sg = seg[n];
        if (sg != cur) {
            atomicAdd(&outSum[cur * ldOut + f], s);
            atomicMax((int*)&outMax[cur * ldOut + f], __float_as_int(mx));
            s = 0.f; mx = 0.f; cur = sg;
        }
        float v = in[(size_t)n * F + f];
        s += v;
        mx = fmaxf(mx, v);
    }
    atomicAdd(&outSum[cur * ldOut + f], s);
    atomicMax((int*)&outMax[cur * ldOut + f], __float_as_int(mx));
}

// Fused dual pool over level-0 nodes: batch pool into z, cover pool into h1cat.
__global__ void dualpool_kernel(const float* __restrict__ h,
                                const int* __restrict__ batch,
                                const int* __restrict__ nodeIdx,
                                const int* __restrict__ clus,
                                int M,
                                float* __restrict__ zSum, float* __restrict__ zMax,
                                float* __restrict__ cSum, float* __restrict__ cMax,
                                int nodesPerBlock) {
    int f = threadIdx.x;
    int n0 = blockIdx.x * nodesPerBlock;
    int n1 = n0 + nodesPerBlock;
    if (n1 > M) n1 = M;
    if (n0 >= n1) return;
    int curB = batch[n0], curC = clus[n0];
    float sB = 0.f, mB = 0.f, sC = 0.f, mC = 0.f;
    for (int n = n0; n < n1; n++) {
        int b = batch[n];
        int cl = clus[n];
        if (b != curB) {
            atomicAdd(&zSum[curB * (4 * HC) + f], sB);
            atomicMax((int*)&zMax[curB * (4 * HC) + f], __float_as_int(mB));
            sB = 0.f; mB = 0.f; curB = b;
        }
        if (cl != curC) {
            atomicAdd(&cSum[curC * (2 * HC) + f], sC);
            atomicMax((int*)&cMax[curC * (2 * HC) + f], __float_as_int(mC));
            sC = 0.f; mC = 0.f; curC = cl;
        }
        float v = h[(size_t)n * HC + f];
        sB += v; mB = fmaxf(mB, v);
        int ni = nodeIdx[n];
        float vc = (ni == n) ? v : h[(size_t)ni * HC + f];
        sC += vc; mC = fmaxf(mC, vc);
    }
    atomicAdd(&zSum[curB * (4 * HC) + f], sB);
    atomicMax((int*)&zMax[curB * (4 * HC) + f], __float_as_int(mB));
    atomicAdd(&cSum[curC * (2 * HC) + f], sC);
    atomicMax((int*)&cMax[curC * (2 * HC) + f], __float_as_int(mC));
}

// ---------------- head ----------------
__global__ void head_kernel(const float* __restrict__ z,
                            const float* __restrict__ gamma,
                            const float* __restrict__ beta,
                            const float* __restrict__ mean,
                            const float* __restrict__ var,
                            const float* __restrict__ W1,
                            const float* __restrict__ b1,
                            const float* __restrict__ W2,
                            const float* __restrict__ b2,
                            float* __restrict__ out) {
    __shared__ float zn[4 * HC];
    __shared__ float s1[HC];
    __shared__ float logits[16];
    int b = blockIdx.x;
    int t = threadIdx.x;
    for (int k = t; k < 4 * HC; k += 256) {
        float v = z[b * 4 * HC + k];
        zn[k] = (v - mean[k]) * rsqrtf(var[k] + 1e-5f) * gamma[k] + beta[k];
    }
    __syncthreads();
    float acc = b1[t];
    for (int k = 0; k < 4 * HC; k++) acc += zn[k] * W1[k * HC + t];
    s1[t] = fmaxf(acc, 0.f);
    __syncthreads();
    if (t < 10) {
        float a2 = b2[t];
        for (int k = 0; k < HC; k++) a2 += s1[k] * W2[k * 10 + t];
        logits[t] = a2;
    }
    __syncthreads();
    if (t == 0) {
        float mx = logits[0];
        for (int c = 1; c < 10; c++) mx = fmaxf(mx, logits[c]);
        float e[10], sum = 0.f;
        for (int c = 0; c < 10; c++) { e[c] = expf(logits[c] - mx); sum += e[c]; }
        float inv = 1.f / sum;
        for (int c = 0; c < 10; c++) out[b * 10 + c] = e[c] * inv;
    }
}

// ---------------- orchestration ----------------
static inline int ceil_div(int a, int b) { return (a + b - 1) / b; }
#define GEMM_SMEM (2 * S_BUF * (int)sizeof(uint32_t))

extern "C" void kernel_launch(void* const* d_in, const int* in_sizes, int n_in,
                              void* d_out, int out_size) {
    const float* x      = (const float*)d_in[0];
    const int*   ei0    = (const int*)d_in[1];
    const float* ew0    = (const float*)d_in[2];
    const int*   batch0 = (const int*)d_in[3];
    const int*   cover  = (const int*)d_in[4];
    const int*   ei1    = (const int*)d_in[5];
    const float* ew1    = (const float*)d_in[6];
    const int*   batch1 = (const int*)d_in[7];
    const float* W_in0  = (const float*)d_in[8];
    const float* b_in0  = (const float*)d_in[9];
    const float* W_in1  = (const float*)d_in[10];
    const float* b_in1  = (const float*)d_in[11];
    const float* W_jk_in= (const float*)d_in[12];
    const float* b_jk_in= (const float*)d_in[13];
    const float* W_b0   = (const float*)d_in[14];
    const float* b_b0   = (const float*)d_in[15];
    const float* W_b1   = (const float*)d_in[16];
    const float* b_b1   = (const float*)d_in[17];
    const float* W_jk_b = (const float*)d_in[18];
    const float* b_jk_b = (const float*)d_in[19];
    const float* bn_g   = (const float*)d_in[20];
    const float* bn_b   = (const float*)d_in[21];
    const float* bn_m   = (const float*)d_in[22];
    const float* bn_v   = (const float*)d_in[23];
    const float* W_lin1 = (const float*)d_in[24];
    const float* b_lin1 = (const float*)d_in[25];
    const float* W_lin2 = (const float*)d_in[26];
    const float* b_lin2 = (const float*)d_in[27];
    float* out = (float*)d_out;

    const int N0 = in_sizes[3];
    const int E0 = in_sizes[2];
    const int N1 = in_sizes[7];
    const int E1 = in_sizes[6];
    const int H = HC;

    const int* row0 = ei0;
    const int* col0 = ei0 + E0;
    const int* nodeC = cover;
    const int* clusC = cover + N0;
    const int* row1 = ei1;
    const int* col1 = ei1 + E1;

    uint32_t *xw, *x1, *x2, *yw, *y1, *y2;
    float *h, *dinv0, *coef0, *h1cat, *hb, *dinv1, *coef1, *z;
    cudaGetSymbolAddress((void**)&xw, g_xw);
    cudaGetSymbolAddress((void**)&x1, g_x1);
    cudaGetSymbolAddress((void**)&x2, g_x2);
    cudaGetSymbolAddress((void**)&h,  g_h);
    cudaGetSymbolAddress((void**)&dinv0, g_dinv0);
    cudaGetSymbolAddress((void**)&coef0, g_coef0);
    cudaGetSymbolAddress((void**)&h1cat, g_h1cat);
    cudaGetSymbolAddress((void**)&yw, g_yw);
    cudaGetSymbolAddress((void**)&y1, g_y1);
    cudaGetSymbolAddress((void**)&y2, g_y2);
    cudaGetSymbolAddress((void**)&hb, g_hb);
    cudaGetSymbolAddress((void**)&dinv1, g_dinv1);
    cudaGetSymbolAddress((void**)&coef1, g_coef1);
    cudaGetSymbolAddress((void**)&z,  g_z);

    int *cnt0, *start0, *cur0, *srow0, *cnt1, *start1, *cur1, *srow1;
    float *scoef0, *scoef1;
    cudaGetSymbolAddress((void**)&cnt0, g_cnt0);
    cudaGetSymbolAddress((void**)&start0, g_start0);
    cudaGetSymbolAddress((void**)&cur0, g_cur0);
    cudaGetSymbolAddress((void**)&srow0, g_srow0);
    cudaGetSymbolAddress((void**)&scoef0, g_scoef0);
    cudaGetSymbolAddress((void**)&cnt1, g_cnt1);
    cudaGetSymbolAddress((void**)&start1, g_start1);
    cudaGetSymbolAddress((void**)&cur1, g_cur1);
    cudaGetSymbolAddress((void**)&srow1, g_srow1);
    cudaGetSymbolAddress((void**)&scoef1, g_scoef1);

    cudaFuncSetAttribute(gemm_tc_kernel,
                         cudaFuncAttributeMaxDynamicSharedMemorySize, GEMM_SMEM);

    dim3 gemmBlk(256);
    dim3 g0(H / GBN, ceil_div(N0, GBM));
    dim3 g1(H / GBN, ceil_div(N1, GBM));

    // ncu (-s 5 -c 1 incl. 2 harness launches) profiles MY 4th launch (the big GEMM).
    fill_kernel<<<ceil_div(N0, 256), 256>>>(dinv0, N0, 1.f);                 // 1
    deg_accum_kernel<<<ceil_div(E0, 256), 256>>>(col0, ew0, dinv0, E0);      // 2
    finalize_dinv_kernel<<<ceil_div(N0, 256), 256>>>(dinv0, N0);             // 3

    // ---- level 0: GCN 1 GEMM (xw = x@W packed, x1 = b+dinv^2*xw packed) ----
    gemm_tc_kernel<<<g0, gemmBlk, GEMM_SMEM>>>(x, x, FC, FC, 0, W_in0, b_in0,
                                               xw, x1, dinv0, N0, H, 0, 0);  // 4 (profiled)

    // ---- level-0 CSR build ----
    edge_coef_kernel<<<ceil_div(E0, 256), 256>>>(row0, col0, ew0, dinv0, coef0, E0);
    filli_kernel<<<ceil_div(N0, 256), 256>>>(cnt0, N0, 0);
    count_kernel<<<ceil_div(E0, 256), 256>>>(col0, cnt0, E0);
    scan_kernel<<<1, 1024>>>(cnt0, start0, cur0, N0);
    emit_kernel<<<ceil_div(E0, 256), 256>>>(row0, col0, coef0, cur0, srow0, scoef0, E0);

    // ---- level 0: GCN 1 aggregate ----
    gcn_gather_csr<<<ceil_div(N0, 4), 256>>>(xw, srow0, scoef0, start0, x1, N0);

    // level-1 prep (independent)
    fill_kernel<<<ceil_div(N1, 256), 256>>>(dinv1, N1, 1.f);
    deg_accum_kernel<<<ceil_div(E1, 256), 256>>>(col1, ew1, dinv1, E1);
    finalize_dinv_kernel<<<ceil_div(N1, 256), 256>>>(dinv1, N1);
    edge_coef_kernel<<<ceil_div(E1, 256), 256>>>(row1, col1, ew1, dinv1, coef1, E1);
    filli_kernel<<<ceil_div(N1, 256), 256>>>(cnt1, N1, 0);
    count_kernel<<<ceil_div(E1, 256), 256>>>(col1, cnt1, E1);
    scan_kernel<<<1, 1024>>>(cnt1, start1, cur1, N1);
    emit_kernel<<<ceil_div(E1, 256), 256>>>(row1, col1, coef1, cur1, srow1, scoef1, E1);
    fill_kernel<<<ceil_div(BC * 4 * H, 256), 256>>>(z, BC * 4 * H, 0.f);
    fill_kernel<<<ceil_div(N1 * 2 * H, 256), 256>>>(h1cat, N1 * 2 * H, 0.f);

    // ---- level 0: GCN 2 (A = x1 packed, relu on load) ----
    gemm_tc_kernel<<<g0, gemmBlk, GEMM_SMEM>>>(x1, x1, H, H, 1, W_in1, b_in1,
                                               xw, x2, dinv0, N0, H, 1, 0);
    gcn_gather_csr<<<ceil_div(N0, 4), 256>>>(xw, srow0, scoef0, start0, x2, N0);

    // ---- level 0: JK cat + linear + relu (A = [x1|x2] packed, C = h fp32) ----
    gemm_tc_kernel<<<g0, gemmBlk, GEMM_SMEM>>>(x1, x2, H, 2 * H, 1, W_jk_in, b_jk_in,
                                               h, NULL, NULL, N0, H, 1, 1);

    // ---- fused level-0 pools (batch -> z, cover -> h1cat) ----
    dualpool_kernel<<<ceil_div(N0, 128), 256>>>(h, batch0, nodeC, clusC, N0,
                                                z + 0, z + H,
                                                h1cat + 0, h1cat + H, 128);

    // ---- level 1: GCN 1 (A = h1cat fp32, K=512) ----
    gemm_tc_kernel<<<g1, gemmBlk, GEMM_SMEM>>>(h1cat, h1cat, 2 * H, 2 * H, 0, W_b0, b_b0,
                                               yw, y1, dinv1, N1, H, 0, 0);
    gcn_gather_csr<<<ceil_div(N1, 4), 256>>>(yw, srow1, scoef1, start1, y1, N1);

    // ---- level 1: GCN 2 ----
    gemm_tc_kernel<<<g1, gemmBlk, GEMM_SMEM>>>(y1, y1, H, H, 1, W_b1, b_b1,
                                               yw, y2, dinv1, N1, H, 1, 0);
    gcn_gather_csr<<<ceil_div(N1, 4), 256>>>(yw, srow1, scoef1, start1, y2, N1);

    // ---- level 1: JK (C = hb fp32) ----
    gemm_tc_kernel<<<g1, gemmBlk, GEMM_SMEM>>>(y1, y2, H, 2 * H, 1, W_jk_b, b_jk_b,
                                               hb, NULL, NULL, N1, H, 1, 1);

    // ---- level-1 batch pool ----
    segpool_kernel<<<ceil_div(N1, 128), 256>>>(hb, batch1, N1, H,
                                               z + 2 * H, z + 3 * H, 4 * H, 128);

    // ---- head ----
    head_kernel<<<BC, 256>>>(z, bn_g, bn_b, bn_m, bn_v,
                             W_lin1, b_lin1, W_lin2, b_lin2, out);
}